// round 1
// baseline (speedup 1.0000x reference)
#include <cuda_runtime.h>
#include <cstdint>

// ---------------------------------------------------------------------------
// Flow net: enc0/1/2 (conv3 s2 + BN + LReLU) -> fusion corr -> dec1/dec0
// (conv3 s1 on concat(feat, upsample)) -> flow (conv1) -> transpose out.
// B=8, N=16384, fp32.
// ---------------------------------------------------------------------------

#define EPSV   1e-5f
#define SLOPEV 0.01f

// scratch layout (floats)
#define OFF_F0   0u            // 8*64*8192   = 4194304
#define OFF_F1   4194304u      // 8*128*4096  = 4194304
#define OFF_F2   8388608u      // 8*256*2048  = 4194304
#define OFF_FEAT 12582912u     // 8*11*2048   = 180224
#define OFF_D1   12763136u     // 8*128*4096  = 4194304
#define OFF_D0   16957440u     // 8*128*8192  = 8388608
#define OFF_FLOW 25346048u     // 8*2*16384   = 262144
#define OFF_SUM  25608192u     // 706
#define OFF_SQS  25608898u     // 706
#define SCRATCH_TOTAL 25609604u

__device__ float g_scratch[SCRATCH_TOTAL];

__device__ __forceinline__ float lrelu(float v) { return v >= 0.f ? v : SLOPEV * v; }

// ---------------------------------------------------------------------------
// zero stats
// ---------------------------------------------------------------------------
__global__ void zero_kernel(float* p, int n) {
    int i = blockIdx.x * 256 + threadIdx.x;
    if (i < n) p[i] = 0.f;
}

// ---------------------------------------------------------------------------
// Generic K=3 conv. Block: 128 threads -> 512 output positions x 8 out chans.
// Input may be a concat of src1 (full res, C1 chans) and src2 (half res,
// C2 chans, nearest-upsampled by indexing p>>1). Zero padding (pad=1).
// ---------------------------------------------------------------------------
template<int STRIDE>
__global__ __launch_bounds__(128)
void conv3_kernel(const float* __restrict__ src1, int C1,
                  const float* __restrict__ src2, int C2,
                  int Lin, int Lout, int Cin, int Cout,
                  const float* __restrict__ w, const float* __restrict__ bias,
                  float* __restrict__ y)
{
    constexpr int TP = 512;
    constexpr int TW = TP * STRIDE + 2;
    constexpr int RS = (TW + 3) & ~3;      // padded row stride (516 / 1028)
    __shared__ float xs[8 * RS];
    __shared__ float ws[8 * 24];           // [ci][k][u], u contiguous

    const int tid = threadIdx.x;
    const int P0  = blockIdx.x * TP;
    const int co0 = blockIdx.y * 8;
    const int b   = blockIdx.z;
    const int L2  = Lin >> 1;

    float acc[4][8];
    #pragma unroll
    for (int j = 0; j < 4; j++)
        #pragma unroll
        for (int u = 0; u < 8; u++) acc[j][u] = 0.f;

    const int pstart = P0 * STRIDE - 1;
    const int ntile  = (Cin + 7) >> 3;

    for (int t = 0; t < ntile; t++) {
        const int ci0 = t * 8;
        const int CTa = min(8, Cin - ci0);
        __syncthreads();
        // stage input tile
        for (int idx = tid; idx < CTa * TW; idx += 128) {
            int ci  = idx / TW;
            int off = idx - ci * TW;
            int p   = pstart + off;
            float v = 0.f;
            if (p >= 0 && p < Lin) {
                int cg = ci0 + ci;
                v = (cg < C1) ? src1[((size_t)(b * C1 + cg)) * Lin + p]
                              : src2[((size_t)(b * C2 + (cg - C1))) * L2 + (p >> 1)];
            }
            xs[ci * RS + off] = v;
        }
        // stage weights: ws[ci*24 + k*8 + u] = w[co0+u][ci0+ci][k]
        for (int idx = tid; idx < CTa * 24; idx += 128) {
            int ci = idx / 24;
            int r  = idx - ci * 24;
            int k  = r >> 3, u = r & 7;
            ws[ci * 24 + k * 8 + u] = w[((size_t)(co0 + u) * Cin + ci0 + ci) * 3 + k];
        }
        __syncthreads();

        for (int ci = 0; ci < CTa; ci++) {
            const float* xr = xs + ci * RS + tid * 4 * STRIDE;
            float xv[4 * STRIDE + 2];
            if (STRIDE == 1) {
                float4 a  = *(const float4*)xr;
                float2 b2 = *(const float2*)(xr + 4);
                xv[0] = a.x; xv[1] = a.y; xv[2] = a.z; xv[3] = a.w;
                xv[4] = b2.x; xv[5] = b2.y;
            } else {
                float4 a  = *(const float4*)xr;
                float4 b4 = *(const float4*)(xr + 4);
                float4 c4 = *(const float4*)(xr + 8);
                xv[0] = a.x; xv[1] = a.y; xv[2] = a.z; xv[3] = a.w;
                xv[4] = b4.x; xv[5] = b4.y; xv[6] = b4.z; xv[7] = b4.w;
                xv[8] = c4.x;
            }
            #pragma unroll
            for (int k = 0; k < 3; k++) {
                float4 w0 = *(const float4*)&ws[ci * 24 + k * 8];
                float4 w1 = *(const float4*)&ws[ci * 24 + k * 8 + 4];
                #pragma unroll
                for (int j = 0; j < 4; j++) {
                    float xq = xv[j * STRIDE + k];
                    acc[j][0] += xq * w0.x; acc[j][1] += xq * w0.y;
                    acc[j][2] += xq * w0.z; acc[j][3] += xq * w0.w;
                    acc[j][4] += xq * w1.x; acc[j][5] += xq * w1.y;
                    acc[j][6] += xq * w1.z; acc[j][7] += xq * w1.w;
                }
            }
        }
    }

    #pragma unroll
    for (int u = 0; u < 8; u++) {
        float bv = bias[co0 + u];
        float4 o = make_float4(acc[0][u] + bv, acc[1][u] + bv,
                               acc[2][u] + bv, acc[3][u] + bv);
        *(float4*)&y[((size_t)(b * Cout + co0 + u)) * Lout + P0 + tid * 4] = o;
    }
}

// ---------------------------------------------------------------------------
// BN batch-stat reduce: per (channel, batch) block -> atomic partials
// ---------------------------------------------------------------------------
__global__ __launch_bounds__(256)
void reduce_kernel(const float* __restrict__ y, int C, int L,
                   float* __restrict__ s_out, float* __restrict__ q_out)
{
    int c = blockIdx.x, b = blockIdx.y;
    const float* p = y + ((size_t)(b * C + c)) * L;
    float s = 0.f, q = 0.f;
    for (int i = threadIdx.x * 4; i < L; i += 1024) {
        float4 v = *(const float4*)(p + i);
        s += v.x + v.y + v.z + v.w;
        q += v.x * v.x + v.y * v.y + v.z * v.z + v.w * v.w;
    }
    unsigned full = 0xffffffffu;
    #pragma unroll
    for (int o = 16; o > 0; o >>= 1) {
        s += __shfl_down_sync(full, s, o);
        q += __shfl_down_sync(full, q, o);
    }
    __shared__ float shs[8], shq[8];
    int wid = threadIdx.x >> 5, lid = threadIdx.x & 31;
    if (lid == 0) { shs[wid] = s; shq[wid] = q; }
    __syncthreads();
    if (threadIdx.x == 0) {
        float ts = 0.f, tq = 0.f;
        #pragma unroll
        for (int i = 0; i < 8; i++) { ts += shs[i]; tq += shq[i]; }
        atomicAdd(&s_out[c], ts);
        atomicAdd(&q_out[c], tq);
    }
}

// ---------------------------------------------------------------------------
// BN apply (in place) + LeakyReLU, vectorized
// ---------------------------------------------------------------------------
__global__ __launch_bounds__(256)
void bn_apply_kernel(float* __restrict__ y, int C, int L,
                     const float* __restrict__ ssum, const float* __restrict__ sqs,
                     const float* __restrict__ gamma, const float* __restrict__ beta,
                     float invn)
{
    size_t i4 = (size_t)blockIdx.x * 256 + threadIdx.x;
    int c = (int)((i4 * 4) / (size_t)L) % C;
    float m   = ssum[c] * invn;
    float var = sqs[c] * invn - m * m;
    float sc  = gamma[c] * rsqrtf(var + EPSV);
    float sh  = beta[c] - sc * m;
    float4 v = ((float4*)y)[i4];
    v.x = lrelu(sc * v.x + sh);
    v.y = lrelu(sc * v.y + sh);
    v.z = lrelu(sc * v.z + sh);
    v.w = lrelu(sc * v.w + sh);
    ((float4*)y)[i4] = v;
}

// ---------------------------------------------------------------------------
// Fusion: banded correlation with K=3 patches, D=5 (f2 vs f2).
// corr[b,d,i] = sum_c sum_t f2[b,c,cl(i+t-1)] * f2[b,c,cl(cl(i+d)+t-1)]
// ---------------------------------------------------------------------------
__global__ __launch_bounds__(128)
void fusion_kernel(const float* __restrict__ f2, float* __restrict__ feat)
{
    const int Nn = 2048, C = 256;
    const int b   = blockIdx.y;
    const int i0  = blockIdx.x * 128;
    const int tid = threadIdx.x;
    const int i   = i0 + tid;
    __shared__ float tile[16][144];

    float acc[11];
    #pragma unroll
    for (int d = 0; d < 11; d++) acc[d] = 0.f;

    const bool interior = (i >= 5) && (i <= Nn - 6);

    for (int c0 = 0; c0 < C; c0 += 16) {
        __syncthreads();
        for (int idx = tid; idx < 16 * 140; idx += 128) {
            int c = idx / 140, off = idx - c * 140;
            int p = i0 - 6 + off;
            p = min(max(p, 0), Nn - 1);
            tile[c][off] = f2[((size_t)(b * C + c0 + c)) * Nn + p];
        }
        __syncthreads();
        for (int c = 0; c < 16; c++) {
            float v[13];
            #pragma unroll
            for (int m = 0; m < 13; m++) v[m] = tile[c][tid + m];
            float A0 = v[5], A1 = v[6], A2 = v[7];
            if (interior) {
                #pragma unroll
                for (int dd = 0; dd < 11; dd++)
                    acc[dd] += A0 * v[dd] + A1 * v[dd + 1] + A2 * v[dd + 2];
            } else {
                for (int dd = 0; dd < 11; dd++) {
                    int j = i + dd - 5;
                    j = min(max(j, 0), Nn - 1);
                    int o0 = max(j - 1, 0) - i0 + 6;
                    int o1 = j - i0 + 6;
                    int o2 = min(j + 1, Nn - 1) - i0 + 6;
                    acc[dd] += A0 * tile[c][o0] + A1 * tile[c][o1] + A2 * tile[c][o2];
                }
            }
        }
    }
    #pragma unroll
    for (int dd = 0; dd < 11; dd++)
        feat[((size_t)(b * 11 + dd)) * Nn + i] = acc[dd];
}

// ---------------------------------------------------------------------------
// Flow head: K=1 conv over concat(x1[1ch @16384], d0[128ch upsampled])
// ---------------------------------------------------------------------------
__global__ __launch_bounds__(256)
void flow_conv_kernel(const float* __restrict__ x1, const float* __restrict__ d0,
                      const float* __restrict__ w, const float* __restrict__ bias,
                      float* __restrict__ out)
{
    const int Nn = 16384;
    int b = blockIdx.y;
    int p = blockIdx.x * 256 + threadIdx.x;
    float xv = x1[(size_t)b * Nn + p];
    float a0 = w[0] * xv;
    float a1 = w[129] * xv;
    const float* dp = d0 + (size_t)b * 128 * 8192 + (p >> 1);
    #pragma unroll 4
    for (int ci = 0; ci < 128; ci++) {
        float v = dp[(size_t)ci * 8192];
        a0 += w[1 + ci] * v;
        a1 += w[130 + ci] * v;
    }
    out[((size_t)(b * 2 + 0)) * Nn + p] = a0 + bias[0];
    out[((size_t)(b * 2 + 1)) * Nn + p] = a1 + bias[1];
}

// ---------------------------------------------------------------------------
// Flow BN apply + LeakyReLU + transpose to (B, N, 2)
// ---------------------------------------------------------------------------
__global__ __launch_bounds__(256)
void flow_apply_kernel(const float* __restrict__ fl,
                       const float* __restrict__ ssum, const float* __restrict__ sqs,
                       const float* __restrict__ gamma, const float* __restrict__ beta,
                       float* __restrict__ out, float invn)
{
    const int Nn = 16384;
    int b = blockIdx.y;
    int p = blockIdx.x * 256 + threadIdx.x;
    float m0 = ssum[0] * invn, m1 = ssum[1] * invn;
    float v0 = sqs[0] * invn - m0 * m0;
    float v1 = sqs[1] * invn - m1 * m1;
    float sc0 = gamma[0] * rsqrtf(v0 + EPSV), sh0 = beta[0] - sc0 * m0;
    float sc1 = gamma[1] * rsqrtf(v1 + EPSV), sh1 = beta[1] - sc1 * m1;
    float a = fl[((size_t)(b * 2 + 0)) * Nn + p];
    float c = fl[((size_t)(b * 2 + 1)) * Nn + p];
    float2 r;
    r.x = lrelu(sc0 * a + sh0);
    r.y = lrelu(sc1 * c + sh1);
    ((float2*)out)[(size_t)b * Nn + p] = r;
}

// ---------------------------------------------------------------------------
extern "C" void kernel_launch(void* const* d_in, const int* in_sizes, int n_in,
                              void* d_out, int out_size)
{
    (void)in_sizes; (void)n_in; (void)out_size;
    const float* scan1 = (const float*)d_in[0];
    const float* e0w = (const float*)d_in[1];
    const float* e0b = (const float*)d_in[2];
    const float* e0g = (const float*)d_in[3];
    const float* e0e = (const float*)d_in[4];
    const float* e1w = (const float*)d_in[5];
    const float* e1b = (const float*)d_in[6];
    const float* e1g = (const float*)d_in[7];
    const float* e1e = (const float*)d_in[8];
    const float* e2w = (const float*)d_in[9];
    const float* e2b = (const float*)d_in[10];
    const float* e2g = (const float*)d_in[11];
    const float* e2e = (const float*)d_in[12];
    const float* d1w = (const float*)d_in[13];
    const float* d1b = (const float*)d_in[14];
    const float* d1g = (const float*)d_in[15];
    const float* d1e = (const float*)d_in[16];
    const float* d0w = (const float*)d_in[17];
    const float* d0b = (const float*)d_in[18];
    const float* d0g = (const float*)d_in[19];
    const float* d0e = (const float*)d_in[20];
    const float* fw  = (const float*)d_in[21];
    const float* fb  = (const float*)d_in[22];
    const float* fg  = (const float*)d_in[23];
    const float* fe  = (const float*)d_in[24];

    float* base = nullptr;
    cudaGetSymbolAddress((void**)&base, g_scratch);
    float* f0   = base + OFF_F0;
    float* f1   = base + OFF_F1;
    float* f2   = base + OFF_F2;
    float* feat = base + OFF_FEAT;
    float* d1   = base + OFF_D1;
    float* d0   = base + OFF_D0;
    float* fl   = base + OFF_FLOW;
    float* sum  = base + OFF_SUM;
    float* sqs  = base + OFF_SQS;

    // stats zero (706 sum + 706 sumsq, contiguous)
    zero_kernel<<<6, 256>>>(sum, 1412);

    // enc0: (B,1,16384) -> (B,64,8192), stride 2
    conv3_kernel<2><<<dim3(16, 8, 8), 128>>>(scan1, 1, nullptr, 0,
                                             16384, 8192, 1, 64, e0w, e0b, f0);
    reduce_kernel<<<dim3(64, 8), 256>>>(f0, 64, 8192, sum + 0, sqs + 0);
    bn_apply_kernel<<<8 * 64 * 8192 / 1024, 256>>>(f0, 64, 8192, sum + 0, sqs + 0,
                                                   e0g, e0e, 1.f / (8.f * 8192.f));

    // enc1: -> (B,128,4096)
    conv3_kernel<2><<<dim3(8, 16, 8), 128>>>(f0, 64, nullptr, 0,
                                             8192, 4096, 64, 128, e1w, e1b, f1);
    reduce_kernel<<<dim3(128, 8), 256>>>(f1, 128, 4096, sum + 64, sqs + 64);
    bn_apply_kernel<<<8 * 128 * 4096 / 1024, 256>>>(f1, 128, 4096, sum + 64, sqs + 64,
                                                    e1g, e1e, 1.f / (8.f * 4096.f));

    // enc2: -> (B,256,2048)
    conv3_kernel<2><<<dim3(4, 32, 8), 128>>>(f1, 128, nullptr, 0,
                                             4096, 2048, 128, 256, e2w, e2b, f2);
    reduce_kernel<<<dim3(256, 8), 256>>>(f2, 256, 2048, sum + 192, sqs + 192);
    bn_apply_kernel<<<8 * 256 * 2048 / 1024, 256>>>(f2, 256, 2048, sum + 192, sqs + 192,
                                                    e2g, e2e, 1.f / (8.f * 2048.f));

    // fusion correlation -> (B,11,2048)
    fusion_kernel<<<dim3(16, 8), 128>>>(f2, feat);

    // dec1: concat(f1[128], up(feat)[11]) -> (B,128,4096), stride 1
    conv3_kernel<1><<<dim3(8, 16, 8), 128>>>(f1, 128, feat, 11,
                                             4096, 4096, 139, 128, d1w, d1b, d1);
    reduce_kernel<<<dim3(128, 8), 256>>>(d1, 128, 4096, sum + 448, sqs + 448);
    bn_apply_kernel<<<8 * 128 * 4096 / 1024, 256>>>(d1, 128, 4096, sum + 448, sqs + 448,
                                                    d1g, d1e, 1.f / (8.f * 4096.f));

    // dec0: concat(f0[64], up(d1)[128]) -> (B,128,8192), stride 1
    conv3_kernel<1><<<dim3(16, 16, 8), 128>>>(f0, 64, d1, 128,
                                              8192, 8192, 192, 128, d0w, d0b, d0);
    reduce_kernel<<<dim3(128, 8), 256>>>(d0, 128, 8192, sum + 576, sqs + 576);
    bn_apply_kernel<<<8 * 128 * 8192 / 1024, 256>>>(d0, 128, 8192, sum + 576, sqs + 576,
                                                    d0g, d0e, 1.f / (8.f * 8192.f));

    // flow head: concat(x1[1], up(d0)[128]) -> (B,2,16384), k=1
    flow_conv_kernel<<<dim3(64, 8), 256>>>(scan1, d0, fw, fb, fl);
    reduce_kernel<<<dim3(2, 8), 256>>>(fl, 2, 16384, sum + 704, sqs + 704);
    flow_apply_kernel<<<dim3(64, 8), 256>>>(fl, sum + 704, sqs + 704, fg, fe,
                                            (float*)d_out, 1.f / (8.f * 16384.f));
}

// round 3
// speedup vs baseline: 1.2837x; 1.2837x over previous
#include <cuda_runtime.h>
#include <cstdint>

// ---------------------------------------------------------------------------
// Flow net: enc0/1/2 (conv3 s2 + BN + LReLU) -> fusion corr -> dec1/dec0
// (conv3 s1 on concat(feat, upsample)) -> flow (conv1) -> transpose out.
// B=8, N=16384, fp32.  R2: f32x2 packed FFMA, unrolled ci-tile, 16 co/block,
// BN-stat reduction fused into conv epilogue.
// ---------------------------------------------------------------------------

#define EPSV   1e-5f
#define SLOPEV 0.01f

// scratch layout (floats)
#define OFF_F0   0u            // 8*64*8192   = 4194304
#define OFF_F1   4194304u      // 8*128*4096  = 4194304
#define OFF_F2   8388608u      // 8*256*2048  = 4194304
#define OFF_FEAT 12582912u     // 8*11*2048   = 180224
#define OFF_D1   12763136u     // 8*128*4096  = 4194304
#define OFF_D0   16957440u     // 8*128*8192  = 8388608
#define OFF_FLOW 25346048u     // 8*2*16384   = 262144
#define OFF_SUM  25608192u     // 706
#define OFF_SQS  25608898u     // 706
#define SCRATCH_TOTAL 25609604u

__device__ float g_scratch[SCRATCH_TOTAL];

__device__ __forceinline__ float lrelu(float v) { return v >= 0.f ? v : SLOPEV * v; }

typedef unsigned long long u64t;

#define FMA2(acc, x, w) \
    asm("fma.rn.f32x2 %0, %1, %2, %0;" : "+l"(acc) : "l"(x), "l"(w))
#define PACK2(out, lo, hi) \
    asm("mov.b64 %0, {%1, %2};" : "=l"(out) : "f"(lo), "f"(hi))
#define UNPACK2(lo, hi, in) \
    asm("mov.b64 {%0, %1}, %2;" : "=f"(lo), "=f"(hi) : "l"(in))

// ---------------------------------------------------------------------------
__global__ void zero_kernel(float* p, int n) {
    int i = blockIdx.x * 256 + threadIdx.x;
    if (i < n) p[i] = 0.f;
}

// ---------------------------------------------------------------------------
// K=3 conv. 128 threads -> 512 output positions x 16 out chans.
// Input: concat of src1 (full res, C1 ch) and src2 (half res, C2 ch,
// nearest-upsampled via p>>1). Zero padding. Epilogue: bias + store +
// fused BN batch-stat partial reduction (atomic to g_sum/g_sqs).
// Packed f32x2 math: channel pairs (2u, 2u+1) share one 64-bit accumulator.
// ---------------------------------------------------------------------------
template<int STRIDE>
__global__ __launch_bounds__(128)
void conv3_kernel(const float* __restrict__ src1, int C1,
                  const float* __restrict__ src2, int C2,
                  int Lin, int Lout, int Cin, int Cout,
                  const float* __restrict__ w, const float* __restrict__ bias,
                  float* __restrict__ y,
                  float* __restrict__ gsum, float* __restrict__ gsqs)
{
    constexpr int TP = 512;
    constexpr int TW = TP * STRIDE + 2;
    constexpr int RS = (TW + 3) & ~3;       // 516 / 1028 floats
    constexpr int XN = 4 * STRIDE + 2;      // 6 / 9 (rounded to 9 below)
    __shared__ __align__(16) float xs[8 * RS];
    __shared__ __align__(16) float ws[8 * 48];   // [ci][k][u16]
    __shared__ float redS[16], redQ[16];

    const int tid = threadIdx.x;
    const int P0  = blockIdx.x * TP;
    const int co0 = blockIdx.y * 16;
    const int b   = blockIdx.z;
    const int L2  = Lin >> 1;

    u64t acc[4][8];
    #pragma unroll
    for (int j = 0; j < 4; j++)
        #pragma unroll
        for (int up = 0; up < 8; up++) acc[j][up] = 0ull;

    const int pstart = P0 * STRIDE - 1;
    const int ntile  = (Cin + 7) >> 3;

    for (int t = 0; t < ntile; t++) {
        const int ci0 = t * 8;
        __syncthreads();
        // stage input tile (always 8 channels; pad with zeros)
        for (int idx = tid; idx < 8 * TW; idx += 128) {
            int ci  = idx / TW;
            int off = idx - ci * TW;
            int p   = pstart + off;
            int cg  = ci0 + ci;
            float v = 0.f;
            if (p >= 0 && p < Lin && cg < Cin) {
                v = (cg < C1) ? src1[((size_t)(b * C1 + cg)) * Lin + p]
                              : src2[((size_t)(b * C2 + (cg - C1))) * L2 + (p >> 1)];
            }
            xs[ci * RS + off] = v;
        }
        // stage weights: ws[ci*48 + k*16 + u] = w[co0+u][ci0+ci][k]
        for (int idx = tid; idx < 8 * 48; idx += 128) {
            int ci = idx / 48;
            int r  = idx - ci * 48;
            int k  = r >> 4, u = r & 15;
            int cg = ci0 + ci;
            ws[ci * 48 + k * 16 + u] =
                (cg < Cin) ? w[((size_t)(co0 + u) * Cin + cg) * 3 + k] : 0.f;
        }
        __syncthreads();

        #pragma unroll
        for (int ci = 0; ci < 8; ci++) {
            const float* xr = xs + ci * RS + tid * 4 * STRIDE;
            float xv[XN];
            if (STRIDE == 1) {
                float4 a  = *(const float4*)xr;
                float2 b2 = *(const float2*)(xr + 4);
                xv[0] = a.x; xv[1] = a.y; xv[2] = a.z; xv[3] = a.w;
                xv[4] = b2.x; xv[5] = b2.y;
            } else {
                float4 a  = *(const float4*)xr;
                float4 b4 = *(const float4*)(xr + 4);
                xv[0] = a.x; xv[1] = a.y; xv[2] = a.z; xv[3] = a.w;
                xv[4] = b4.x; xv[5] = b4.y; xv[6] = b4.z; xv[7] = b4.w;
                xv[8] = xr[8];
            }
            u64t xp[XN];
            #pragma unroll
            for (int m = 0; m < XN; m++) PACK2(xp[m], xv[m], xv[m]);

            #pragma unroll
            for (int k = 0; k < 3; k++) {
                const u64t* wsp = (const u64t*)(ws + ci * 48 + k * 16);
                u64t wp[8];
                #pragma unroll
                for (int up = 0; up < 8; up++) wp[up] = wsp[up];
                #pragma unroll
                for (int j = 0; j < 4; j++) {
                    u64t xq = xp[j * STRIDE + k];
                    #pragma unroll
                    for (int up = 0; up < 8; up++) FMA2(acc[j][up], xq, wp[up]);
                }
            }
        }
    }

    // epilogue: bias + store + fused BN-stat block reduction
    __syncthreads();
    if (tid < 16) { redS[tid] = 0.f; redQ[tid] = 0.f; }
    __syncthreads();

    const int lid = tid & 31;
    #pragma unroll
    for (int up = 0; up < 8; up++) {
        float o0[4], o1[4];
        #pragma unroll
        for (int j = 0; j < 4; j++) UNPACK2(o0[j], o1[j], acc[j][up]);
        int c0 = co0 + 2 * up;
        float b0 = bias[c0], b1 = bias[c0 + 1];
        float s0 = 0.f, q0 = 0.f, s1 = 0.f, q1 = 0.f;
        #pragma unroll
        for (int j = 0; j < 4; j++) {
            o0[j] += b0; o1[j] += b1;
            s0 += o0[j]; q0 += o0[j] * o0[j];
            s1 += o1[j]; q1 += o1[j] * o1[j];
        }
        *(float4*)&y[((size_t)(b * Cout + c0)) * Lout + P0 + tid * 4] =
            make_float4(o0[0], o0[1], o0[2], o0[3]);
        *(float4*)&y[((size_t)(b * Cout + c0 + 1)) * Lout + P0 + tid * 4] =
            make_float4(o1[0], o1[1], o1[2], o1[3]);
        unsigned full = 0xffffffffu;
        #pragma unroll
        for (int o = 16; o > 0; o >>= 1) {
            s0 += __shfl_down_sync(full, s0, o);
            q0 += __shfl_down_sync(full, q0, o);
            s1 += __shfl_down_sync(full, s1, o);
            q1 += __shfl_down_sync(full, q1, o);
        }
        if (lid == 0) {
            atomicAdd(&redS[2 * up], s0);     atomicAdd(&redQ[2 * up], q0);
            atomicAdd(&redS[2 * up + 1], s1); atomicAdd(&redQ[2 * up + 1], q1);
        }
    }
    __syncthreads();
    if (tid < 16) {
        atomicAdd(&gsum[co0 + tid], redS[tid]);
        atomicAdd(&gsqs[co0 + tid], redQ[tid]);
    }
}

// ---------------------------------------------------------------------------
// BN apply (in place) + LeakyReLU, vectorized
// ---------------------------------------------------------------------------
__global__ __launch_bounds__(256)
void bn_apply_kernel(float* __restrict__ y, int C, int L,
                     const float* __restrict__ ssum, const float* __restrict__ sqs,
                     const float* __restrict__ gamma, const float* __restrict__ beta,
                     float invn)
{
    size_t i4 = (size_t)blockIdx.x * 256 + threadIdx.x;
    int c = (int)((i4 * 4) / (size_t)L) % C;
    float m   = ssum[c] * invn;
    float var = sqs[c] * invn - m * m;
    float sc  = gamma[c] * rsqrtf(var + EPSV);
    float sh  = beta[c] - sc * m;
    float4 v = ((float4*)y)[i4];
    v.x = lrelu(sc * v.x + sh);
    v.y = lrelu(sc * v.y + sh);
    v.z = lrelu(sc * v.z + sh);
    v.w = lrelu(sc * v.w + sh);
    ((float4*)y)[i4] = v;
}

// ---------------------------------------------------------------------------
// BN batch-stat reduce (flow head only, C=2)
// ---------------------------------------------------------------------------
__global__ __launch_bounds__(256)
void reduce_kernel(const float* __restrict__ y, int C, int L,
                   float* __restrict__ s_out, float* __restrict__ q_out)
{
    int c = blockIdx.x, b = blockIdx.y;
    const float* p = y + ((size_t)(b * C + c)) * L;
    float s = 0.f, q = 0.f;
    for (int i = threadIdx.x * 4; i < L; i += 1024) {
        float4 v = *(const float4*)(p + i);
        s += v.x + v.y + v.z + v.w;
        q += v.x * v.x + v.y * v.y + v.z * v.z + v.w * v.w;
    }
    unsigned full = 0xffffffffu;
    #pragma unroll
    for (int o = 16; o > 0; o >>= 1) {
        s += __shfl_down_sync(full, s, o);
        q += __shfl_down_sync(full, q, o);
    }
    __shared__ float shs[8], shq[8];
    int wid = threadIdx.x >> 5, lid = threadIdx.x & 31;
    if (lid == 0) { shs[wid] = s; shq[wid] = q; }
    __syncthreads();
    if (threadIdx.x == 0) {
        float ts = 0.f, tq = 0.f;
        #pragma unroll
        for (int i = 0; i < 8; i++) { ts += shs[i]; tq += shq[i]; }
        atomicAdd(&s_out[c], ts);
        atomicAdd(&q_out[c], tq);
    }
}

// ---------------------------------------------------------------------------
// Fusion: banded correlation with K=3 patches, D=5 (f2 vs f2).
// ---------------------------------------------------------------------------
__global__ __launch_bounds__(128)
void fusion_kernel(const float* __restrict__ f2, float* __restrict__ feat)
{
    const int Nn = 2048, C = 256;
    const int b   = blockIdx.y;
    const int i0  = blockIdx.x * 128;
    const int tid = threadIdx.x;
    const int i   = i0 + tid;
    __shared__ float tile[16][144];

    float acc[11];
    #pragma unroll
    for (int d = 0; d < 11; d++) acc[d] = 0.f;

    const bool interior = (i >= 5) && (i <= Nn - 6);

    for (int c0 = 0; c0 < C; c0 += 16) {
        __syncthreads();
        for (int idx = tid; idx < 16 * 140; idx += 128) {
            int c = idx / 140, off = idx - c * 140;
            int p = i0 - 6 + off;
            p = min(max(p, 0), Nn - 1);
            tile[c][off] = f2[((size_t)(b * C + c0 + c)) * Nn + p];
        }
        __syncthreads();
        for (int c = 0; c < 16; c++) {
            float v[13];
            #pragma unroll
            for (int m = 0; m < 13; m++) v[m] = tile[c][tid + m];
            float A0 = v[5], A1 = v[6], A2 = v[7];
            if (interior) {
                #pragma unroll
                for (int dd = 0; dd < 11; dd++)
                    acc[dd] += A0 * v[dd] + A1 * v[dd + 1] + A2 * v[dd + 2];
            } else {
                for (int dd = 0; dd < 11; dd++) {
                    int j = i + dd - 5;
                    j = min(max(j, 0), Nn - 1);
                    int o0 = max(j - 1, 0) - i0 + 6;
                    int o1 = j - i0 + 6;
                    int o2 = min(j + 1, Nn - 1) - i0 + 6;
                    acc[dd] += A0 * tile[c][o0] + A1 * tile[c][o1] + A2 * tile[c][o2];
                }
            }
        }
    }
    #pragma unroll
    for (int dd = 0; dd < 11; dd++)
        feat[((size_t)(b * 11 + dd)) * Nn + i] = acc[dd];
}

// ---------------------------------------------------------------------------
// Flow head: K=1 conv over concat(x1[1ch @16384], d0[128ch upsampled])
// ---------------------------------------------------------------------------
__global__ __launch_bounds__(256)
void flow_conv_kernel(const float* __restrict__ x1, const float* __restrict__ d0,
                      const float* __restrict__ w, const float* __restrict__ bias,
                      float* __restrict__ out)
{
    const int Nn = 16384;
    int b = blockIdx.y;
    int p = blockIdx.x * 256 + threadIdx.x;
    float xv = x1[(size_t)b * Nn + p];
    float a0 = w[0] * xv;
    float a1 = w[129] * xv;
    const float* dp = d0 + (size_t)b * 128 * 8192 + (p >> 1);
    #pragma unroll 4
    for (int ci = 0; ci < 128; ci++) {
        float v = dp[(size_t)ci * 8192];
        a0 += w[1 + ci] * v;
        a1 += w[130 + ci] * v;
    }
    out[((size_t)(b * 2 + 0)) * Nn + p] = a0 + bias[0];
    out[((size_t)(b * 2 + 1)) * Nn + p] = a1 + bias[1];
}

// ---------------------------------------------------------------------------
// Flow BN apply + LeakyReLU + transpose to (B, N, 2)
// ---------------------------------------------------------------------------
__global__ __launch_bounds__(256)
void flow_apply_kernel(const float* __restrict__ fl,
                       const float* __restrict__ ssum, const float* __restrict__ sqs,
                       const float* __restrict__ gamma, const float* __restrict__ beta,
                       float* __restrict__ out, float invn)
{
    const int Nn = 16384;
    int b = blockIdx.y;
    int p = blockIdx.x * 256 + threadIdx.x;
    float m0 = ssum[0] * invn, m1 = ssum[1] * invn;
    float v0 = sqs[0] * invn - m0 * m0;
    float v1 = sqs[1] * invn - m1 * m1;
    float sc0 = gamma[0] * rsqrtf(v0 + EPSV), sh0 = beta[0] - sc0 * m0;
    float sc1 = gamma[1] * rsqrtf(v1 + EPSV), sh1 = beta[1] - sc1 * m1;
    float a = fl[((size_t)(b * 2 + 0)) * Nn + p];
    float c = fl[((size_t)(b * 2 + 1)) * Nn + p];
    float2 r;
    r.x = lrelu(sc0 * a + sh0);
    r.y = lrelu(sc1 * c + sh1);
    ((float2*)out)[(size_t)b * Nn + p] = r;
}

// ---------------------------------------------------------------------------
extern "C" void kernel_launch(void* const* d_in, const int* in_sizes, int n_in,
                              void* d_out, int out_size)
{
    (void)in_sizes; (void)n_in; (void)out_size;
    const float* scan1 = (const float*)d_in[0];
    const float* e0w = (const float*)d_in[1];
    const float* e0b = (const float*)d_in[2];
    const float* e0g = (const float*)d_in[3];
    const float* e0e = (const float*)d_in[4];
    const float* e1w = (const float*)d_in[5];
    const float* e1b = (const float*)d_in[6];
    const float* e1g = (const float*)d_in[7];
    const float* e1e = (const float*)d_in[8];
    const float* e2w = (const float*)d_in[9];
    const float* e2b = (const float*)d_in[10];
    const float* e2g = (const float*)d_in[11];
    const float* e2e = (const float*)d_in[12];
    const float* d1w = (const float*)d_in[13];
    const float* d1b = (const float*)d_in[14];
    const float* d1g = (const float*)d_in[15];
    const float* d1e = (const float*)d_in[16];
    const float* d0w = (const float*)d_in[17];
    const float* d0b = (const float*)d_in[18];
    const float* d0g = (const float*)d_in[19];
    const float* d0e = (const float*)d_in[20];
    const float* fw  = (const float*)d_in[21];
    const float* fb  = (const float*)d_in[22];
    const float* fg  = (const float*)d_in[23];
    const float* fe  = (const float*)d_in[24];

    float* base = nullptr;
    cudaGetSymbolAddress((void**)&base, g_scratch);
    float* f0   = base + OFF_F0;
    float* f1   = base + OFF_F1;
    float* f2   = base + OFF_F2;
    float* feat = base + OFF_FEAT;
    float* d1   = base + OFF_D1;
    float* d0   = base + OFF_D0;
    float* fl   = base + OFF_FLOW;
    float* sum  = base + OFF_SUM;
    float* sqs  = base + OFF_SQS;

    zero_kernel<<<6, 256>>>(sum, 1412);

    // enc0: (B,1,16384) -> (B,64,8192), stride 2
    conv3_kernel<2><<<dim3(16, 4, 8), 128>>>(scan1, 1, nullptr, 0,
                                             16384, 8192, 1, 64, e0w, e0b, f0,
                                             sum + 0, sqs + 0);
    bn_apply_kernel<<<8 * 64 * 8192 / 1024, 256>>>(f0, 64, 8192, sum + 0, sqs + 0,
                                                   e0g, e0e, 1.f / (8.f * 8192.f));

    // enc1: -> (B,128,4096)
    conv3_kernel<2><<<dim3(8, 8, 8), 128>>>(f0, 64, nullptr, 0,
                                            8192, 4096, 64, 128, e1w, e1b, f1,
                                            sum + 64, sqs + 64);
    bn_apply_kernel<<<8 * 128 * 4096 / 1024, 256>>>(f1, 128, 4096, sum + 64, sqs + 64,
                                                    e1g, e1e, 1.f / (8.f * 4096.f));

    // enc2: -> (B,256,2048)
    conv3_kernel<2><<<dim3(4, 16, 8), 128>>>(f1, 128, nullptr, 0,
                                             4096, 2048, 128, 256, e2w, e2b, f2,
                                             sum + 192, sqs + 192);
    bn_apply_kernel<<<8 * 256 * 2048 / 1024, 256>>>(f2, 256, 2048, sum + 192, sqs + 192,
                                                    e2g, e2e, 1.f / (8.f * 2048.f));

    // fusion correlation -> (B,11,2048)
    fusion_kernel<<<dim3(16, 8), 128>>>(f2, feat);

    // dec1: concat(f1[128], up(feat)[11]) -> (B,128,4096), stride 1
    conv3_kernel<1><<<dim3(8, 8, 8), 128>>>(f1, 128, feat, 11,
                                            4096, 4096, 139, 128, d1w, d1b, d1,
                                            sum + 448, sqs + 448);
    bn_apply_kernel<<<8 * 128 * 4096 / 1024, 256>>>(d1, 128, 4096, sum + 448, sqs + 448,
                                                    d1g, d1e, 1.f / (8.f * 4096.f));

    // dec0: concat(f0[64], up(d1)[128]) -> (B,128,8192), stride 1
    conv3_kernel<1><<<dim3(16, 8, 8), 128>>>(f0, 64, d1, 128,
                                             8192, 8192, 192, 128, d0w, d0b, d0,
                                             sum + 576, sqs + 576);
    bn_apply_kernel<<<8 * 128 * 8192 / 1024, 256>>>(d0, 128, 8192, sum + 576, sqs + 576,
                                                    d0g, d0e, 1.f / (8.f * 8192.f));

    // flow head: concat(x1[1], up(d0)[128]) -> (B,2,16384), k=1
    flow_conv_kernel<<<dim3(64, 8), 256>>>(scan1, d0, fw, fb, fl);
    reduce_kernel<<<dim3(2, 8), 256>>>(fl, 2, 16384, sum + 704, sqs + 704);
    flow_apply_kernel<<<dim3(64, 8), 256>>>(fl, sum + 704, sqs + 704, fg, fe,
                                            (float*)d_out, 1.f / (8.f * 16384.f));
}

// round 4
// speedup vs baseline: 1.8187x; 1.4167x over previous
#include <cuda_runtime.h>
#include <cstdint>

// ---------------------------------------------------------------------------
// Flow net R4: BN+LReLU fused into consumer staging, float4 staging,
// 4pos x 8ch/thread @256 threads, f32x2 packed math.
// ---------------------------------------------------------------------------

#define EPSV   1e-5f
#define SLOPEV 0.01f

#define OFF_F0   0u            // 8*64*8192
#define OFF_F1   4194304u      // 8*128*4096
#define OFF_F2   8388608u      // 8*256*2048
#define OFF_FEAT 12582912u     // 8*11*2048
#define OFF_D1   12763136u     // 8*128*4096
#define OFF_D0   16957440u     // 8*128*8192
#define OFF_FLOW 25346048u     // 8*2*16384
#define OFF_SUM  25608192u     // 706
#define OFF_SQS  25608898u     // 706
#define SCRATCH_TOTAL 25609604u

__device__ float g_scratch[SCRATCH_TOTAL];

typedef unsigned long long u64t;

#define FMA2(acc, x, w) \
    asm("fma.rn.f32x2 %0, %1, %2, %0;" : "+l"(acc) : "l"(x), "l"(w))
#define PACK2(out, lo, hi) \
    asm("mov.b64 %0, {%1, %2};" : "=l"(out) : "f"(lo), "f"(hi))
#define UNPACK2(lo, hi, in) \
    asm("mov.b64 {%0, %1}, %2;" : "=f"(lo), "=f"(hi) : "l"(in))

__device__ __forceinline__ float bnl(float r, float sc, float sh, float sl) {
    float a = sc * r + sh;
    return a >= 0.f ? a : sl * a;
}

// ---------------------------------------------------------------------------
__global__ void zero_kernel(float* p, int n) {
    int i = blockIdx.x * 256 + threadIdx.x;
    if (i < n) p[i] = 0.f;
}

// ---------------------------------------------------------------------------
// K=3 conv, 256 threads -> 1024 positions x 8 out channels.
// Inputs staged with fused BN+LReLU (per-source params; null => identity).
// src2 (if any) is half-resolution, nearest-upsampled via p>>1.
// Epilogue: bias + store + fused BN-stat partial reduction.
// ---------------------------------------------------------------------------
template<int STRIDE, int CT>
__global__ __launch_bounds__(256)
void conv3_kernel(const float* __restrict__ src1, int C1,
                  const float* __restrict__ s1sum, const float* __restrict__ s1sqs,
                  const float* __restrict__ s1g, const float* __restrict__ s1be, float inv1,
                  const float* __restrict__ src2, int C2,
                  const float* __restrict__ s2sum, const float* __restrict__ s2sqs,
                  const float* __restrict__ s2g, const float* __restrict__ s2be, float inv2,
                  int Lin, int Lout, int Cin, int Cout,
                  const float* __restrict__ w, const float* __restrict__ bias,
                  float* __restrict__ y,
                  float* __restrict__ gsum, float* __restrict__ gsqs)
{
    constexpr int TP    = 1024;
    constexpr int TWpad = TP * STRIDE + 8;
    constexpr int NV    = TWpad / 4;

    __shared__ __align__(16) float xs[CT * TWpad];
    __shared__ __align__(16) float ws[CT * 24];
    __shared__ float csc[192], csh[192], csl[192];
    __shared__ float redS[8], redQ[8];

    const int tid = threadIdx.x;
    const int P0  = blockIdx.x * TP;
    const int co0 = blockIdx.y * 8;
    const int b   = blockIdx.z;
    const int L2  = Lin >> 1;
    const int hs  = P0 * STRIDE - 4;

    // per-channel BN params for staging
    for (int c = tid; c < Cin; c += 256) {
        float sc = 1.f, sh = 0.f, sl = 1.f;
        if (c < C1) {
            if (s1sum) {
                float m = s1sum[c] * inv1;
                float var = s1sqs[c] * inv1 - m * m;
                sc = s1g[c] * rsqrtf(var + EPSV);
                sh = s1be[c] - sc * m;
                sl = SLOPEV;
            }
        } else {
            int c2 = c - C1;
            if (s2sum) {
                float m = s2sum[c2] * inv2;
                float var = s2sqs[c2] * inv2 - m * m;
                sc = s2g[c2] * rsqrtf(var + EPSV);
                sh = s2be[c2] - sc * m;
                sl = SLOPEV;
            }
        }
        csc[c] = sc; csh[c] = sh; csl[c] = sl;
    }
    if (tid < 8) { redS[tid] = 0.f; redQ[tid] = 0.f; }

    u64t acc[4][4];
    #pragma unroll
    for (int j = 0; j < 4; j++)
        #pragma unroll
        for (int u = 0; u < 4; u++) acc[j][u] = 0ull;

    const int ntile = (Cin + CT - 1) / CT;

    for (int t = 0; t < ntile; t++) {
        const int ci0 = t * CT;
        __syncthreads();
        // stage input tile: whole float4s, single in-range predicate
        for (int idx = tid; idx < CT * NV; idx += 256) {
            int ci  = idx / NV;
            int off = (idx - ci * NV) * 4;
            int p   = hs + off;
            int cg  = ci0 + ci;
            float4 v = make_float4(0.f, 0.f, 0.f, 0.f);
            if (cg < Cin && p >= 0 && p < Lin) {
                float sc = csc[cg], sh = csh[cg], sl = csl[cg];
                if (cg < C1) {
                    float4 r = *(const float4*)&src1[(size_t)(b * C1 + cg) * Lin + p];
                    v.x = bnl(r.x, sc, sh, sl); v.y = bnl(r.y, sc, sh, sl);
                    v.z = bnl(r.z, sc, sh, sl); v.w = bnl(r.w, sc, sh, sl);
                } else {
                    float2 r = *(const float2*)&src2[(size_t)(b * C2 + (cg - C1)) * L2 + (p >> 1)];
                    float a = bnl(r.x, sc, sh, sl);
                    float c2v = bnl(r.y, sc, sh, sl);
                    v.x = a; v.y = a; v.z = c2v; v.w = c2v;
                }
            }
            *(float4*)&xs[ci * TWpad + off] = v;
        }
        // stage weights: ws[ci*24 + k*8 + u] = w[co0+u][ci0+ci][k]
        for (int idx = tid; idx < CT * 24; idx += 256) {
            int ci = idx / 24;
            int r  = idx - ci * 24;
            int k  = r >> 3, u = r & 7;
            int cg = ci0 + ci;
            ws[ci * 24 + k * 8 + u] =
                (cg < Cin) ? w[((size_t)(co0 + u) * Cin + cg) * 3 + k] : 0.f;
        }
        __syncthreads();

        #pragma unroll
        for (int ci = 0; ci < CT; ci++) {
            const float* xr = xs + ci * TWpad + tid * 4 * STRIDE;
            float xv[4 * STRIDE + 9];
            {
                float4 a0 = *(const float4*)xr;
                float4 a1 = *(const float4*)(xr + 4);
                xv[0] = a0.x; xv[1] = a0.y; xv[2] = a0.z; xv[3] = a0.w;
                xv[4] = a1.x; xv[5] = a1.y; xv[6] = a1.z; xv[7] = a1.w;
                if (STRIDE == 1) {
                    xv[8] = xr[8];
                } else {
                    float4 a2 = *(const float4*)(xr + 8);
                    xv[8] = a2.x; xv[9] = a2.y; xv[10] = a2.z; xv[11] = a2.w;
                    xv[12] = xr[12];
                }
            }
            #pragma unroll
            for (int k = 0; k < 3; k++) {
                const u64t* wq = (const u64t*)(ws + ci * 24 + k * 8);
                u64t w0 = wq[0], w1 = wq[1], w2 = wq[2], w3 = wq[3];
                #pragma unroll
                for (int j = 0; j < 4; j++) {
                    float xsc = xv[j * STRIDE + k + 3];
                    u64t xq;
                    PACK2(xq, xsc, xsc);
                    FMA2(acc[j][0], xq, w0);
                    FMA2(acc[j][1], xq, w1);
                    FMA2(acc[j][2], xq, w2);
                    FMA2(acc[j][3], xq, w3);
                }
            }
        }
    }

    // epilogue: bias + store + fused BN-stat reduction
    __syncthreads();
    const int lid = tid & 31;
    #pragma unroll
    for (int u = 0; u < 4; u++) {
        float o0[4], o1[4];
        #pragma unroll
        for (int j = 0; j < 4; j++) UNPACK2(o0[j], o1[j], acc[j][u]);
        int c0 = co0 + 2 * u;
        float b0 = bias[c0], b1 = bias[c0 + 1];
        float s0 = 0.f, q0 = 0.f, s1 = 0.f, q1 = 0.f;
        #pragma unroll
        for (int j = 0; j < 4; j++) {
            o0[j] += b0; o1[j] += b1;
            s0 += o0[j]; q0 += o0[j] * o0[j];
            s1 += o1[j]; q1 += o1[j] * o1[j];
        }
        *(float4*)&y[((size_t)(b * Cout + c0)) * Lout + P0 + tid * 4] =
            make_float4(o0[0], o0[1], o0[2], o0[3]);
        *(float4*)&y[((size_t)(b * Cout + c0 + 1)) * Lout + P0 + tid * 4] =
            make_float4(o1[0], o1[1], o1[2], o1[3]);
        unsigned full = 0xffffffffu;
        #pragma unroll
        for (int o = 16; o > 0; o >>= 1) {
            s0 += __shfl_down_sync(full, s0, o);
            q0 += __shfl_down_sync(full, q0, o);
            s1 += __shfl_down_sync(full, s1, o);
            q1 += __shfl_down_sync(full, q1, o);
        }
        if (lid == 0) {
            atomicAdd(&redS[2 * u], s0);     atomicAdd(&redQ[2 * u], q0);
            atomicAdd(&redS[2 * u + 1], s1); atomicAdd(&redQ[2 * u + 1], q1);
        }
    }
    __syncthreads();
    if (tid < 8) {
        atomicAdd(&gsum[co0 + tid], redS[tid]);
        atomicAdd(&gsqs[co0 + tid], redQ[tid]);
    }
}

// ---------------------------------------------------------------------------
// BN batch-stat reduce (flow head only, C=2)
// ---------------------------------------------------------------------------
__global__ __launch_bounds__(256)
void reduce_kernel(const float* __restrict__ y, int C, int L,
                   float* __restrict__ s_out, float* __restrict__ q_out)
{
    int c = blockIdx.x, b = blockIdx.y;
    const float* p = y + ((size_t)(b * C + c)) * L;
    float s = 0.f, q = 0.f;
    for (int i = threadIdx.x * 4; i < L; i += 1024) {
        float4 v = *(const float4*)(p + i);
        s += v.x + v.y + v.z + v.w;
        q += v.x * v.x + v.y * v.y + v.z * v.z + v.w * v.w;
    }
    unsigned full = 0xffffffffu;
    #pragma unroll
    for (int o = 16; o > 0; o >>= 1) {
        s += __shfl_down_sync(full, s, o);
        q += __shfl_down_sync(full, q, o);
    }
    __shared__ float shs[8], shq[8];
    int wid = threadIdx.x >> 5, lid = threadIdx.x & 31;
    if (lid == 0) { shs[wid] = s; shq[wid] = q; }
    __syncthreads();
    if (threadIdx.x == 0) {
        float ts = 0.f, tq = 0.f;
        #pragma unroll
        for (int i = 0; i < 8; i++) { ts += shs[i]; tq += shq[i]; }
        atomicAdd(&s_out[c], ts);
        atomicAdd(&q_out[c], tq);
    }
}

// ---------------------------------------------------------------------------
// Fusion: banded correlation, K=3 patch, D=5 (f2 vs f2). BN+LReLU of f2
// fused into staging.
// ---------------------------------------------------------------------------
__global__ __launch_bounds__(128)
void fusion_kernel(const float* __restrict__ f2, float* __restrict__ feat,
                   const float* __restrict__ ssum, const float* __restrict__ sqs,
                   const float* __restrict__ gamma, const float* __restrict__ beta,
                   float invn)
{
    const int Nn = 2048, C = 256;
    const int b   = blockIdx.y;
    const int i0  = blockIdx.x * 128;
    const int tid = threadIdx.x;
    const int i   = i0 + tid;
    __shared__ float tile[16][144];
    __shared__ float csc[256], csh[256];

    for (int c = tid; c < C; c += 128) {
        float m = ssum[c] * invn;
        float var = sqs[c] * invn - m * m;
        float sc = gamma[c] * rsqrtf(var + EPSV);
        csc[c] = sc;
        csh[c] = beta[c] - sc * m;
    }

    float acc[11];
    #pragma unroll
    for (int d = 0; d < 11; d++) acc[d] = 0.f;

    const bool interior = (i >= 5) && (i <= Nn - 6);

    for (int c0 = 0; c0 < C; c0 += 16) {
        __syncthreads();
        for (int idx = tid; idx < 16 * 140; idx += 128) {
            int c = idx / 140, off = idx - c * 140;
            int p = i0 - 6 + off;
            p = min(max(p, 0), Nn - 1);
            float r = f2[((size_t)(b * C + c0 + c)) * Nn + p];
            tile[c][off] = bnl(r, csc[c0 + c], csh[c0 + c], SLOPEV);
        }
        __syncthreads();
        for (int c = 0; c < 16; c++) {
            float v[13];
            #pragma unroll
            for (int m = 0; m < 13; m++) v[m] = tile[c][tid + m];
            float A0 = v[5], A1 = v[6], A2 = v[7];
            if (interior) {
                #pragma unroll
                for (int dd = 0; dd < 11; dd++)
                    acc[dd] += A0 * v[dd] + A1 * v[dd + 1] + A2 * v[dd + 2];
            } else {
                for (int dd = 0; dd < 11; dd++) {
                    int j = i + dd - 5;
                    j = min(max(j, 0), Nn - 1);
                    int o0 = max(j - 1, 0) - i0 + 6;
                    int o1 = j - i0 + 6;
                    int o2 = min(j + 1, Nn - 1) - i0 + 6;
                    acc[dd] += A0 * tile[c][o0] + A1 * tile[c][o1] + A2 * tile[c][o2];
                }
            }
        }
    }
    #pragma unroll
    for (int dd = 0; dd < 11; dd++)
        feat[((size_t)(b * 11 + dd)) * Nn + i] = acc[dd];
}

// ---------------------------------------------------------------------------
// Flow head: K=1 conv over concat(x1[1ch raw], d0[128ch, BN+LReLU fused,
// upsampled]).
// ---------------------------------------------------------------------------
__global__ __launch_bounds__(256)
void flow_conv_kernel(const float* __restrict__ x1, const float* __restrict__ d0,
                      const float* __restrict__ w, const float* __restrict__ bias,
                      const float* __restrict__ ssum, const float* __restrict__ sqs,
                      const float* __restrict__ gamma, const float* __restrict__ beta,
                      float invn,
                      float* __restrict__ out)
{
    const int Nn = 16384;
    __shared__ float csc[128], csh[128];
    int tid = threadIdx.x;
    if (tid < 128) {
        float m = ssum[tid] * invn;
        float var = sqs[tid] * invn - m * m;
        float sc = gamma[tid] * rsqrtf(var + EPSV);
        csc[tid] = sc;
        csh[tid] = beta[tid] - sc * m;
    }
    __syncthreads();

    int b = blockIdx.y;
    int p = blockIdx.x * 256 + tid;
    float xv = x1[(size_t)b * Nn + p];
    float a0 = w[0] * xv;
    float a1 = w[129] * xv;
    const float* dp = d0 + (size_t)b * 128 * 8192 + (p >> 1);
    #pragma unroll 4
    for (int ci = 0; ci < 128; ci++) {
        float r = dp[(size_t)ci * 8192];
        float v = bnl(r, csc[ci], csh[ci], SLOPEV);
        a0 += w[1 + ci] * v;
        a1 += w[130 + ci] * v;
    }
    out[((size_t)(b * 2 + 0)) * Nn + p] = a0 + bias[0];
    out[((size_t)(b * 2 + 1)) * Nn + p] = a1 + bias[1];
}

// ---------------------------------------------------------------------------
// Flow BN apply + LeakyReLU + transpose to (B, N, 2)
// ---------------------------------------------------------------------------
__global__ __launch_bounds__(256)
void flow_apply_kernel(const float* __restrict__ fl,
                       const float* __restrict__ ssum, const float* __restrict__ sqs,
                       const float* __restrict__ gamma, const float* __restrict__ beta,
                       float* __restrict__ out, float invn)
{
    const int Nn = 16384;
    int b = blockIdx.y;
    int p = blockIdx.x * 256 + threadIdx.x;
    float m0 = ssum[0] * invn, m1 = ssum[1] * invn;
    float v0 = sqs[0] * invn - m0 * m0;
    float v1 = sqs[1] * invn - m1 * m1;
    float sc0 = gamma[0] * rsqrtf(v0 + EPSV), sh0 = beta[0] - sc0 * m0;
    float sc1 = gamma[1] * rsqrtf(v1 + EPSV), sh1 = beta[1] - sc1 * m1;
    float a = fl[((size_t)(b * 2 + 0)) * Nn + p];
    float c = fl[((size_t)(b * 2 + 1)) * Nn + p];
    float2 r;
    r.x = bnl(a, sc0, sh0, SLOPEV) * 0.f + (sc0 * a + sh0 >= 0.f ? sc0 * a + sh0 : SLOPEV * (sc0 * a + sh0));
    r.x = bnl(a, sc0, sh0, SLOPEV);
    r.y = bnl(c, sc1, sh1, SLOPEV);
    ((float2*)out)[(size_t)b * Nn + p] = r;
}

// ---------------------------------------------------------------------------
extern "C" void kernel_launch(void* const* d_in, const int* in_sizes, int n_in,
                              void* d_out, int out_size)
{
    (void)in_sizes; (void)n_in; (void)out_size;
    const float* scan1 = (const float*)d_in[0];
    const float* e0w = (const float*)d_in[1];
    const float* e0b = (const float*)d_in[2];
    const float* e0g = (const float*)d_in[3];
    const float* e0e = (const float*)d_in[4];
    const float* e1w = (const float*)d_in[5];
    const float* e1b = (const float*)d_in[6];
    const float* e1g = (const float*)d_in[7];
    const float* e1e = (const float*)d_in[8];
    const float* e2w = (const float*)d_in[9];
    const float* e2b = (const float*)d_in[10];
    const float* e2g = (const float*)d_in[11];
    const float* e2e = (const float*)d_in[12];
    const float* d1w = (const float*)d_in[13];
    const float* d1b = (const float*)d_in[14];
    const float* d1g = (const float*)d_in[15];
    const float* d1e = (const float*)d_in[16];
    const float* d0w = (const float*)d_in[17];
    const float* d0b = (const float*)d_in[18];
    const float* d0g = (const float*)d_in[19];
    const float* d0e = (const float*)d_in[20];
    const float* fw  = (const float*)d_in[21];
    const float* fb  = (const float*)d_in[22];
    const float* fg  = (const float*)d_in[23];
    const float* fe  = (const float*)d_in[24];

    float* base = nullptr;
    cudaGetSymbolAddress((void**)&base, g_scratch);
    float* f0   = base + OFF_F0;
    float* f1   = base + OFF_F1;
    float* f2   = base + OFF_F2;
    float* feat = base + OFF_FEAT;
    float* d1   = base + OFF_D1;
    float* d0   = base + OFF_D0;
    float* fl   = base + OFF_FLOW;
    float* sum  = base + OFF_SUM;
    float* sqs  = base + OFF_SQS;

    const float i0n = 1.f / (8.f * 8192.f);
    const float i1n = 1.f / (8.f * 4096.f);
    const float i2n = 1.f / (8.f * 2048.f);

    zero_kernel<<<6, 256>>>(sum, 1412);

    // enc0: scan1 raw -> f0 (pre-BN), stride 2
    conv3_kernel<2, 4><<<dim3(8, 8, 8), 256>>>(
        scan1, 1, nullptr, nullptr, nullptr, nullptr, 0.f,
        nullptr, 0, nullptr, nullptr, nullptr, nullptr, 0.f,
        16384, 8192, 1, 64, e0w, e0b, f0, sum + 0, sqs + 0);

    // enc1: bn(f0) -> f1 (pre-BN), stride 2
    conv3_kernel<2, 4><<<dim3(4, 16, 8), 256>>>(
        f0, 64, sum + 0, sqs + 0, e0g, e0e, i0n,
        nullptr, 0, nullptr, nullptr, nullptr, nullptr, 0.f,
        8192, 4096, 64, 128, e1w, e1b, f1, sum + 64, sqs + 64);

    // enc2: bn(f1) -> f2 (pre-BN), stride 2
    conv3_kernel<2, 4><<<dim3(2, 32, 8), 256>>>(
        f1, 128, sum + 64, sqs + 64, e1g, e1e, i1n,
        nullptr, 0, nullptr, nullptr, nullptr, nullptr, 0.f,
        4096, 2048, 128, 256, e2w, e2b, f2, sum + 192, sqs + 192);

    // fusion on bn(f2) -> feat (raw)
    fusion_kernel<<<dim3(16, 8), 128>>>(f2, feat,
                                        sum + 192, sqs + 192, e2g, e2e, i2n);

    // dec1: concat(bn(f1), up(feat)) -> d1 (pre-BN), stride 1
    conv3_kernel<1, 8><<<dim3(4, 16, 8), 256>>>(
        f1, 128, sum + 64, sqs + 64, e1g, e1e, i1n,
        feat, 11, nullptr, nullptr, nullptr, nullptr, 0.f,
        4096, 4096, 139, 128, d1w, d1b, d1, sum + 448, sqs + 448);

    // dec0: concat(bn(f0), up(bn(d1))) -> d0 (pre-BN), stride 1
    conv3_kernel<1, 8><<<dim3(8, 16, 8), 256>>>(
        f0, 64, sum + 0, sqs + 0, e0g, e0e, i0n,
        d1, 128, sum + 448, sqs + 448, d1g, d1e, i1n,
        8192, 8192, 192, 128, d0w, d0b, d0, sum + 576, sqs + 576);

    // flow head: concat(x1 raw, up(bn(d0))), k=1
    flow_conv_kernel<<<dim3(64, 8), 256>>>(scan1, d0, fw, fb,
                                           sum + 576, sqs + 576, d0g, d0e, i0n,
                                           fl);
    reduce_kernel<<<dim3(2, 8), 256>>>(fl, 2, 16384, sum + 704, sqs + 704);
    flow_apply_kernel<<<dim3(64, 8), 256>>>(fl, sum + 704, sqs + 704, fg, fe,
                                            (float*)d_out, 1.f / (8.f * 16384.f));
}

// round 5
// speedup vs baseline: 2.4521x; 1.3483x over previous
#include <cuda_runtime.h>
#include <cstdint>

// ---------------------------------------------------------------------------
// Flow net R5: cp.async double-buffered convs (pure-copy staging),
// standalone BN+LReLU transform passes (materializing upsampled versions),
// all-weights-staged-once, f32x2 packed math.
// ---------------------------------------------------------------------------

#define EPSV   1e-5f
#define SLOPEV 0.01f

// scratch layout (floats)
#define OFF_F0R    0u          // raw enc0 out      8*64*8192  = 4194304
#define OFF_T0     4194304u    // bn(f0)
#define OFF_F1R    8388608u    // raw enc1 out      8*128*4096 = 4194304
#define OFF_T1     12582912u   // bn(f1)
#define OFF_F2R    16777216u   // raw enc2 out      8*256*2048 = 4194304
#define OFF_T2     20971520u   // bn(f2)
#define OFF_FEATUP 25165824u   // fusion out, upsampled  8*11*4096 = 360448
#define OFF_D1R    25526272u   // raw dec1 out      4194304
#define OFF_D1UP   29720576u   // bn(d1) upsampled  8*128*8192 = 8388608
#define OFF_D0R    38109184u   // raw dec0 out      8388608
#define OFF_FL     46497792u   // flow raw          262144
#define OFF_SUM    46759936u   // 706
#define OFF_SQS    46760642u   // 706
#define SCRATCH_TOTAL 46761348u

__device__ float g_scratch[SCRATCH_TOTAL];

typedef unsigned long long u64t;

#define FMA2(acc, x, w) \
    asm("fma.rn.f32x2 %0, %1, %2, %0;" : "+l"(acc) : "l"(x), "l"(w))
#define PACK2(out, lo, hi) \
    asm("mov.b64 %0, {%1, %2};" : "=l"(out) : "f"(lo), "f"(hi))
#define UNPACK2(lo, hi, in) \
    asm("mov.b64 {%0, %1}, %2;" : "=f"(lo), "=f"(hi) : "l"(in))

__device__ __forceinline__ float bnl(float r, float sc, float sh) {
    float a = sc * r + sh;
    return a >= 0.f ? a : SLOPEV * a;
}

__device__ __forceinline__ void cp16(unsigned dst, const float* src, int bytes) {
    asm volatile("cp.async.ca.shared.global [%0], [%1], 16, %2;"
                 :: "r"(dst), "l"(src), "r"(bytes));
}

// ---------------------------------------------------------------------------
__global__ void zero_kernel(float* p, int n) {
    int i = blockIdx.x * 256 + threadIdx.x;
    if (i < n) p[i] = 0.f;
}

// ---------------------------------------------------------------------------
// K=3 conv, cp.async double-buffered. 256 threads -> 1024 positions x 8 outch.
// src1/src2 both full-resolution, pre-transformed. Pure-copy staging.
// Epilogue: bias + store raw + fused BN-stat partial reduction.
// ---------------------------------------------------------------------------
template<int STRIDE, int CT>
__global__ __launch_bounds__(256, 2)
void conv3_cp(const float* __restrict__ src1, int C1,
              const float* __restrict__ src2, int C2,
              int Lin, int Lout, int Cin, int CinPad,
              const float* __restrict__ w, const float* __restrict__ bias,
              float* __restrict__ y,
              float* __restrict__ gsum, float* __restrict__ gsqs)
{
    constexpr int TP = 1024;
    constexpr int TW = TP * STRIDE + 8;
    constexpr int NV = TW / 4;
    constexpr int XN = 4 * STRIDE + 5;   // 9 (s1) / 13 (s2)

    extern __shared__ float sh[];
    __shared__ float redS[8], redQ[8];

    const int tid = threadIdx.x;
    const int P0  = blockIdx.x * TP;
    const int co0 = blockIdx.y * 8;
    const int b   = blockIdx.z;
    const int hs  = P0 * STRIDE - 4;
    const int wsN = CinPad * 24;
    float* ws = sh;
    float* xs = sh + wsN;

    if (tid < 8) { redS[tid] = 0.f; redQ[tid] = 0.f; }

    // stage ALL weights once: ws[ci*24 + k*8 + u] = w[co0+u][ci][k]
    for (int idx = tid; idx < wsN; idx += 256) {
        int ci = idx / 24;
        int r  = idx - ci * 24;
        int k  = r >> 3, u = r & 7;
        ws[idx] = (ci < Cin) ? w[((size_t)(co0 + u) * Cin + ci) * 3 + k] : 0.f;
    }

    u64t acc[4][4];
    #pragma unroll
    for (int j = 0; j < 4; j++)
        #pragma unroll
        for (int u = 0; u < 4; u++) acc[j][u] = 0ull;

    const int ntile = CinPad / CT;

    auto stage = [&](int t, int buf) {
        float* xb = xs + buf * (CT * TW);
        int ci0 = t * CT;
        #pragma unroll
        for (int ci = 0; ci < CT; ci++) {
            int cg = ci0 + ci;
            bool cv = (cg < Cin);
            const float* row;
            if (cg < C1)      row = src1 + (size_t)(b * C1 + cg) * Lin;
            else if (cv)      row = src2 + (size_t)(b * C2 + (cg - C1)) * Lin;
            else              row = src1;
            unsigned sb = (unsigned)__cvta_generic_to_shared(xb + ci * TW);
            for (int v = tid; v < NV; v += 256) {
                int p   = hs + v * 4;
                int okb = (cv && p >= 0 && p < Lin) ? 16 : 0;
                int pc  = min(max(p, 0), Lin - 4);
                cp16(sb + v * 16, row + pc, okb);
            }
        }
    };

    stage(0, 0);
    asm volatile("cp.async.commit_group;");

    for (int t = 0; t < ntile; t++) {
        asm volatile("cp.async.wait_group 0;");
        __syncthreads();
        if (t + 1 < ntile) {
            stage(t + 1, (t + 1) & 1);
            asm volatile("cp.async.commit_group;");
        }
        const float* xbc = xs + (t & 1) * (CT * TW);
        #pragma unroll
        for (int ci = 0; ci < CT; ci++) {
            int gci = t * CT + ci;
            const float* xr = xbc + ci * TW + tid * 4 * STRIDE;
            float xv[XN];
            {
                float4 a0 = *(const float4*)xr;
                float4 a1 = *(const float4*)(xr + 4);
                xv[0] = a0.x; xv[1] = a0.y; xv[2] = a0.z; xv[3] = a0.w;
                xv[4] = a1.x; xv[5] = a1.y; xv[6] = a1.z; xv[7] = a1.w;
                if (STRIDE == 1) {
                    xv[8] = xr[8];
                } else {
                    float4 a2 = *(const float4*)(xr + 8);
                    xv[8] = a2.x; xv[9] = a2.y; xv[10] = a2.z; xv[11] = a2.w;
                    xv[12] = 0.f;
                }
            }
            const u64t* wrow = (const u64t*)(ws + gci * 24);
            #pragma unroll
            for (int k = 0; k < 3; k++) {
                u64t w0 = wrow[k * 4 + 0], w1 = wrow[k * 4 + 1];
                u64t w2 = wrow[k * 4 + 2], w3 = wrow[k * 4 + 3];
                #pragma unroll
                for (int j = 0; j < 4; j++) {
                    float xsc = xv[j * STRIDE + k + 3];
                    u64t xq;
                    PACK2(xq, xsc, xsc);
                    FMA2(acc[j][0], xq, w0);
                    FMA2(acc[j][1], xq, w1);
                    FMA2(acc[j][2], xq, w2);
                    FMA2(acc[j][3], xq, w3);
                }
            }
        }
    }

    // epilogue: bias + raw store + fused BN-stat reduction
    const int lid = tid & 31;
    #pragma unroll
    for (int u = 0; u < 4; u++) {
        float o0[4], o1[4];
        #pragma unroll
        for (int j = 0; j < 4; j++) UNPACK2(o0[j], o1[j], acc[j][u]);
        int c0 = co0 + 2 * u;
        float b0 = bias[c0], b1 = bias[c0 + 1];
        float s0 = 0.f, q0 = 0.f, s1 = 0.f, q1 = 0.f;
        #pragma unroll
        for (int j = 0; j < 4; j++) {
            o0[j] += b0; o1[j] += b1;
            s0 += o0[j]; q0 += o0[j] * o0[j];
            s1 += o1[j]; q1 += o1[j] * o1[j];
        }
        *(float4*)&y[((size_t)(b * (gridDim.y * 8) + c0)) * Lout + P0 + tid * 4] =
            make_float4(o0[0], o0[1], o0[2], o0[3]);
        *(float4*)&y[((size_t)(b * (gridDim.y * 8) + c0 + 1)) * Lout + P0 + tid * 4] =
            make_float4(o1[0], o1[1], o1[2], o1[3]);
        unsigned full = 0xffffffffu;
        #pragma unroll
        for (int o = 16; o > 0; o >>= 1) {
            s0 += __shfl_down_sync(full, s0, o);
            q0 += __shfl_down_sync(full, q0, o);
            s1 += __shfl_down_sync(full, s1, o);
            q1 += __shfl_down_sync(full, q1, o);
        }
        if (lid == 0) {
            atomicAdd(&redS[2 * u], s0);     atomicAdd(&redQ[2 * u], q0);
            atomicAdd(&redS[2 * u + 1], s1); atomicAdd(&redQ[2 * u + 1], q1);
        }
    }
    __syncthreads();
    if (tid < 8) {
        atomicAdd(&gsum[co0 + tid], redS[tid]);
        atomicAdd(&gsqs[co0 + tid], redQ[tid]);
    }
}

// ---------------------------------------------------------------------------
// BN apply -> separate output (same resolution)
// ---------------------------------------------------------------------------
__global__ __launch_bounds__(256)
void bn_out_kernel(const float* __restrict__ raw, float* __restrict__ out,
                   int C, int L,
                   const float* __restrict__ ssum, const float* __restrict__ sqs,
                   const float* __restrict__ g, const float* __restrict__ be,
                   float invn)
{
    size_t i4 = (size_t)blockIdx.x * 256 + threadIdx.x;
    int c = (int)((i4 * 4) / (size_t)L) % C;
    float m   = ssum[c] * invn;
    float var = sqs[c] * invn - m * m;
    float sc  = g[c] * rsqrtf(var + EPSV);
    float sh  = be[c] - sc * m;
    float4 v = ((const float4*)raw)[i4];
    float4 o;
    o.x = bnl(v.x, sc, sh); o.y = bnl(v.y, sc, sh);
    o.z = bnl(v.z, sc, sh); o.w = bnl(v.w, sc, sh);
    ((float4*)out)[i4] = o;
}

// ---------------------------------------------------------------------------
// BN apply + nearest-upsample x2 -> separate output (double resolution)
// ---------------------------------------------------------------------------
__global__ __launch_bounds__(256)
void bn_up2_kernel(const float* __restrict__ raw, float* __restrict__ out,
                   int C, int Lin,
                   const float* __restrict__ ssum, const float* __restrict__ sqs,
                   const float* __restrict__ g, const float* __restrict__ be,
                   float invn)
{
    size_t i2 = (size_t)blockIdx.x * 256 + threadIdx.x;   // over B*C*Lin/2
    int c = (int)((i2 * 2) / (size_t)Lin) % C;
    float m   = ssum[c] * invn;
    float var = sqs[c] * invn - m * m;
    float sc  = g[c] * rsqrtf(var + EPSV);
    float sh  = be[c] - sc * m;
    float2 v = ((const float2*)raw)[i2];
    float a = bnl(v.x, sc, sh);
    float d = bnl(v.y, sc, sh);
    ((float4*)out)[i2] = make_float4(a, a, d, d);
}

// ---------------------------------------------------------------------------
// BN batch-stat reduce (flow head only, C=2)
// ---------------------------------------------------------------------------
__global__ __launch_bounds__(256)
void reduce_kernel(const float* __restrict__ y, int C, int L,
                   float* __restrict__ s_out, float* __restrict__ q_out)
{
    int c = blockIdx.x, b = blockIdx.y;
    const float* p = y + ((size_t)(b * C + c)) * L;
    float s = 0.f, q = 0.f;
    for (int i = threadIdx.x * 4; i < L; i += 1024) {
        float4 v = *(const float4*)(p + i);
        s += v.x + v.y + v.z + v.w;
        q += v.x * v.x + v.y * v.y + v.z * v.z + v.w * v.w;
    }
    unsigned full = 0xffffffffu;
    #pragma unroll
    for (int o = 16; o > 0; o >>= 1) {
        s += __shfl_down_sync(full, s, o);
        q += __shfl_down_sync(full, q, o);
    }
    __shared__ float shs[8], shq[8];
    int wid = threadIdx.x >> 5, lid = threadIdx.x & 31;
    if (lid == 0) { shs[wid] = s; shq[wid] = q; }
    __syncthreads();
    if (threadIdx.x == 0) {
        float ts = 0.f, tq = 0.f;
        #pragma unroll
        for (int i = 0; i < 8; i++) { ts += shs[i]; tq += shq[i]; }
        atomicAdd(&s_out[c], ts);
        atomicAdd(&q_out[c], tq);
    }
}

// ---------------------------------------------------------------------------
// Fusion: banded correlation, K=3 patch, D=5, on pre-transformed t2.
// Writes feat directly upsampled x2 (duplicated) to (B, 11, 4096).
// ---------------------------------------------------------------------------
__global__ __launch_bounds__(128)
void fusion_kernel(const float* __restrict__ t2, float* __restrict__ featup)
{
    const int Nn = 2048, C = 256;
    const int b   = blockIdx.y;
    const int i0  = blockIdx.x * 128;
    const int tid = threadIdx.x;
    const int i   = i0 + tid;
    __shared__ float tile[16][144];

    float acc[11];
    #pragma unroll
    for (int d = 0; d < 11; d++) acc[d] = 0.f;

    const bool interior = (i >= 5) && (i <= Nn - 6);

    for (int c0 = 0; c0 < C; c0 += 16) {
        __syncthreads();
        for (int idx = tid; idx < 16 * 140; idx += 128) {
            int c = idx / 140, off = idx - c * 140;
            int p = i0 - 6 + off;
            p = min(max(p, 0), Nn - 1);
            tile[c][off] = t2[((size_t)(b * C + c0 + c)) * Nn + p];
        }
        __syncthreads();
        for (int c = 0; c < 16; c++) {
            float v[13];
            #pragma unroll
            for (int m = 0; m < 13; m++) v[m] = tile[c][tid + m];
            float A0 = v[5], A1 = v[6], A2 = v[7];
            if (interior) {
                #pragma unroll
                for (int dd = 0; dd < 11; dd++)
                    acc[dd] += A0 * v[dd] + A1 * v[dd + 1] + A2 * v[dd + 2];
            } else {
                for (int dd = 0; dd < 11; dd++) {
                    int j = i + dd - 5;
                    j = min(max(j, 0), Nn - 1);
                    int o0 = max(j - 1, 0) - i0 + 6;
                    int o1 = j - i0 + 6;
                    int o2 = min(j + 1, Nn - 1) - i0 + 6;
                    acc[dd] += A0 * tile[c][o0] + A1 * tile[c][o1] + A2 * tile[c][o2];
                }
            }
        }
    }
    #pragma unroll
    for (int dd = 0; dd < 11; dd++) {
        float2* fo = (float2*)&featup[((size_t)(b * 11 + dd)) * 4096];
        fo[i] = make_float2(acc[dd], acc[dd]);
    }
}

// ---------------------------------------------------------------------------
// Flow head: K=1 conv over concat(x1 raw, up(bn(d0))) with BN fused on d0.
// ---------------------------------------------------------------------------
__global__ __launch_bounds__(256)
void flow_conv_kernel(const float* __restrict__ x1, const float* __restrict__ d0,
                      const float* __restrict__ w, const float* __restrict__ bias,
                      const float* __restrict__ ssum, const float* __restrict__ sqs,
                      const float* __restrict__ gamma, const float* __restrict__ beta,
                      float invn,
                      float* __restrict__ out)
{
    const int Nn = 16384;
    __shared__ float csc[128], csh[128];
    int tid = threadIdx.x;
    if (tid < 128) {
        float m = ssum[tid] * invn;
        float var = sqs[tid] * invn - m * m;
        float sc = gamma[tid] * rsqrtf(var + EPSV);
        csc[tid] = sc;
        csh[tid] = beta[tid] - sc * m;
    }
    __syncthreads();

    int b = blockIdx.y;
    int p = blockIdx.x * 256 + tid;
    float xv = x1[(size_t)b * Nn + p];
    float a0 = w[0] * xv;
    float a1 = w[129] * xv;
    const float* dp = d0 + (size_t)b * 128 * 8192 + (p >> 1);
    #pragma unroll 4
    for (int ci = 0; ci < 128; ci++) {
        float r = dp[(size_t)ci * 8192];
        float v = bnl(r, csc[ci], csh[ci]);
        a0 += w[1 + ci] * v;
        a1 += w[130 + ci] * v;
    }
    out[((size_t)(b * 2 + 0)) * Nn + p] = a0 + bias[0];
    out[((size_t)(b * 2 + 1)) * Nn + p] = a1 + bias[1];
}

// ---------------------------------------------------------------------------
// Flow BN apply + LeakyReLU + transpose to (B, N, 2)
// ---------------------------------------------------------------------------
__global__ __launch_bounds__(256)
void flow_apply_kernel(const float* __restrict__ fl,
                       const float* __restrict__ ssum, const float* __restrict__ sqs,
                       const float* __restrict__ gamma, const float* __restrict__ beta,
                       float* __restrict__ out, float invn)
{
    const int Nn = 16384;
    int b = blockIdx.y;
    int p = blockIdx.x * 256 + threadIdx.x;
    float m0 = ssum[0] * invn, m1 = ssum[1] * invn;
    float v0 = sqs[0] * invn - m0 * m0;
    float v1 = sqs[1] * invn - m1 * m1;
    float sc0 = gamma[0] * rsqrtf(v0 + EPSV), sh0 = beta[0] - sc0 * m0;
    float sc1 = gamma[1] * rsqrtf(v1 + EPSV), sh1 = beta[1] - sc1 * m1;
    float a = fl[((size_t)(b * 2 + 0)) * Nn + p];
    float c = fl[((size_t)(b * 2 + 1)) * Nn + p];
    float2 r;
    r.x = bnl(a, sc0, sh0);
    r.y = bnl(c, sc1, sh1);
    ((float2*)out)[(size_t)b * Nn + p] = r;
}

// ---------------------------------------------------------------------------
extern "C" void kernel_launch(void* const* d_in, const int* in_sizes, int n_in,
                              void* d_out, int out_size)
{
    (void)in_sizes; (void)n_in; (void)out_size;
    const float* scan1 = (const float*)d_in[0];
    const float* e0w = (const float*)d_in[1];
    const float* e0b = (const float*)d_in[2];
    const float* e0g = (const float*)d_in[3];
    const float* e0e = (const float*)d_in[4];
    const float* e1w = (const float*)d_in[5];
    const float* e1b = (const float*)d_in[6];
    const float* e1g = (const float*)d_in[7];
    const float* e1e = (const float*)d_in[8];
    const float* e2w = (const float*)d_in[9];
    const float* e2b = (const float*)d_in[10];
    const float* e2g = (const float*)d_in[11];
    const float* e2e = (const float*)d_in[12];
    const float* d1w = (const float*)d_in[13];
    const float* d1b = (const float*)d_in[14];
    const float* d1g = (const float*)d_in[15];
    const float* d1e = (const float*)d_in[16];
    const float* d0w = (const float*)d_in[17];
    const float* d0b = (const float*)d_in[18];
    const float* d0g = (const float*)d_in[19];
    const float* d0e = (const float*)d_in[20];
    const float* fw  = (const float*)d_in[21];
    const float* fb  = (const float*)d_in[22];
    const float* fg  = (const float*)d_in[23];
    const float* fe  = (const float*)d_in[24];

    float* base = nullptr;
    cudaGetSymbolAddress((void**)&base, g_scratch);
    float* f0r    = base + OFF_F0R;
    float* t0     = base + OFF_T0;
    float* f1r    = base + OFF_F1R;
    float* t1     = base + OFF_T1;
    float* f2r    = base + OFF_F2R;
    float* t2     = base + OFF_T2;
    float* featup = base + OFF_FEATUP;
    float* d1r    = base + OFF_D1R;
    float* d1up   = base + OFF_D1UP;
    float* d0r    = base + OFF_D0R;
    float* fl     = base + OFF_FL;
    float* sum    = base + OFF_SUM;
    float* sqs    = base + OFF_SQS;

    const float i0n = 1.f / (8.f * 8192.f);
    const float i1n = 1.f / (8.f * 4096.f);
    const float i2n = 1.f / (8.f * 2048.f);

    // dynamic smem sizes (bytes)
    const int SM21 = (1 * 24 + 2 * 1 * 2056) * 4;      // 16544
    const int SM24 = (128 * 24 + 2 * 4 * 2056) * 4;    // 78080 (max of enc1/enc2)
    const int SM18 = (192 * 24 + 2 * 8 * 1032) * 4;    // 84480 (max of dec1/dec0)
    cudaFuncSetAttribute(conv3_cp<2, 1>, cudaFuncAttributeMaxDynamicSharedMemorySize, SM21);
    cudaFuncSetAttribute(conv3_cp<2, 4>, cudaFuncAttributeMaxDynamicSharedMemorySize, SM24);
    cudaFuncSetAttribute(conv3_cp<1, 8>, cudaFuncAttributeMaxDynamicSharedMemorySize, SM18);

    zero_kernel<<<6, 256>>>(sum, 1412);

    // enc0: scan1 (B,1,16384) -> f0r (B,64,8192)
    conv3_cp<2, 1><<<dim3(8, 8, 8), 256, SM21>>>(
        scan1, 1, nullptr, 0, 16384, 8192, 1, 1,
        e0w, e0b, f0r, sum + 0, sqs + 0);
    bn_out_kernel<<<4096, 256>>>(f0r, t0, 64, 8192, sum + 0, sqs + 0, e0g, e0e, i0n);

    // enc1: t0 -> f1r (B,128,4096)
    conv3_cp<2, 4><<<dim3(4, 16, 8), 256, (64 * 24 + 2 * 4 * 2056) * 4>>>(
        t0, 64, nullptr, 0, 8192, 4096, 64, 64,
        e1w, e1b, f1r, sum + 64, sqs + 64);
    bn_out_kernel<<<4096, 256>>>(f1r, t1, 128, 4096, sum + 64, sqs + 64, e1g, e1e, i1n);

    // enc2: t1 -> f2r (B,256,2048)
    conv3_cp<2, 4><<<dim3(2, 32, 8), 256, SM24>>>(
        t1, 128, nullptr, 0, 4096, 2048, 128, 128,
        e2w, e2b, f2r, sum + 192, sqs + 192);
    bn_out_kernel<<<4096, 256>>>(f2r, t2, 256, 2048, sum + 192, sqs + 192, e2g, e2e, i2n);

    // fusion on t2 -> featup (B,11,4096) pre-upsampled
    fusion_kernel<<<dim3(16, 8), 128>>>(t2, featup);

    // dec1: concat(t1[128], featup[11]) -> d1r (B,128,4096)
    conv3_cp<1, 8><<<dim3(4, 16, 8), 256, (144 * 24 + 2 * 8 * 1032) * 4>>>(
        t1, 128, featup, 11, 4096, 4096, 139, 144,
        d1w, d1b, d1r, sum + 448, sqs + 448);
    bn_up2_kernel<<<8192, 256>>>(d1r, d1up, 128, 4096, sum + 448, sqs + 448, d1g, d1e, i1n);

    // dec0: concat(t0[64], d1up[128]) -> d0r (B,128,8192)
    conv3_cp<1, 8><<<dim3(8, 16, 8), 256, SM18>>>(
        t0, 64, d1up, 128, 8192, 8192, 192, 192,
        d0w, d0b, d0r, sum + 576, sqs + 576);

    // flow head
    flow_conv_kernel<<<dim3(64, 8), 256>>>(scan1, d0r, fw, fb,
                                           sum + 576, sqs + 576, d0g, d0e, i0n, fl);
    reduce_kernel<<<dim3(2, 8), 256>>>(fl, 2, 16384, sum + 704, sqs + 704);
    flow_apply_kernel<<<dim3(64, 8), 256>>>(fl, sum + 704, sqs + 704, fg, fe,
                                            (float*)d_out, 1.f / (8.f * 16384.f));
}

// round 6
// speedup vs baseline: 2.5407x; 1.0361x over previous
#include <cuda_runtime.h>
#include <cstdint>

// ---------------------------------------------------------------------------
// Flow net R6: occupancy-tuned cp.async convs (3 blocks/SM), BN fused into
// fusion staging (t2 pass deleted), channel-parallel fusion, paired flow head.
// ---------------------------------------------------------------------------

#define EPSV   1e-5f
#define SLOPEV 0.01f

// scratch layout (floats)
#define OFF_F0R    0u          // raw enc0 out      8*64*8192  = 4194304
#define OFF_T0     4194304u    // bn(f0)
#define OFF_F1R    8388608u    // raw enc1 out      8*128*4096 = 4194304
#define OFF_T1     12582912u   // bn(f1)
#define OFF_F2R    16777216u   // raw enc2 out      8*256*2048 = 4194304
#define OFF_FEATUP 20971520u   // fusion out, upsampled  8*11*4096 = 360448
#define OFF_D1R    21331968u   // raw dec1 out      4194304
#define OFF_D1UP   25526272u   // bn(d1) upsampled  8*128*8192 = 8388608
#define OFF_D0R    33914880u   // raw dec0 out      8388608
#define OFF_FL     42303488u   // flow raw          262144
#define OFF_SUM    42565632u   // 706
#define OFF_SQS    42566338u   // 706
#define SCRATCH_TOTAL 42567044u

__device__ float g_scratch[SCRATCH_TOTAL];

typedef unsigned long long u64t;

#define FMA2(acc, x, w) \
    asm("fma.rn.f32x2 %0, %1, %2, %0;" : "+l"(acc) : "l"(x), "l"(w))
#define PACK2(out, lo, hi) \
    asm("mov.b64 %0, {%1, %2};" : "=l"(out) : "f"(lo), "f"(hi))
#define UNPACK2(lo, hi, in) \
    asm("mov.b64 {%0, %1}, %2;" : "=f"(lo), "=f"(hi) : "l"(in))

__device__ __forceinline__ float bnl(float r, float sc, float sh) {
    float a = sc * r + sh;
    return a >= 0.f ? a : SLOPEV * a;
}

__device__ __forceinline__ void cp16(unsigned dst, const float* src, int bytes) {
    asm volatile("cp.async.ca.shared.global [%0], [%1], 16, %2;"
                 :: "r"(dst), "l"(src), "r"(bytes));
}

// ---------------------------------------------------------------------------
__global__ void zero_kernel(float* p, int n) {
    int i = blockIdx.x * 256 + threadIdx.x;
    if (i < n) p[i] = 0.f;
}

// ---------------------------------------------------------------------------
// K=3 conv, cp.async double-buffered. 256 threads -> 1024 positions x 8 outch.
// src1/src2 both full-resolution, pre-transformed. Pure-copy staging.
// Epilogue: bias + store raw + fused BN-stat partial reduction.
// ---------------------------------------------------------------------------
template<int STRIDE, int CT>
__global__ __launch_bounds__(256, 3)
void conv3_cp(const float* __restrict__ src1, int C1,
              const float* __restrict__ src2, int C2,
              int Lin, int Lout, int Cin, int CinPad,
              const float* __restrict__ w, const float* __restrict__ bias,
              float* __restrict__ y,
              float* __restrict__ gsum, float* __restrict__ gsqs)
{
    constexpr int TP = 1024;
    constexpr int TW = TP * STRIDE + 8;
    constexpr int NV = TW / 4;
    constexpr int XN = 4 * STRIDE + 5;   // 9 (s1) / 13 (s2)

    extern __shared__ float sh[];
    __shared__ float redS[8], redQ[8];

    const int tid = threadIdx.x;
    const int P0  = blockIdx.x * TP;
    const int co0 = blockIdx.y * 8;
    const int b   = blockIdx.z;
    const int hs  = P0 * STRIDE - 4;
    const int wsN = CinPad * 24;
    float* ws = sh;
    float* xs = sh + wsN;

    if (tid < 8) { redS[tid] = 0.f; redQ[tid] = 0.f; }

    // stage ALL weights once: ws[ci*24 + k*8 + u] = w[co0+u][ci][k]
    for (int idx = tid; idx < wsN; idx += 256) {
        int ci = idx / 24;
        int r  = idx - ci * 24;
        int k  = r >> 3, u = r & 7;
        ws[idx] = (ci < Cin) ? w[((size_t)(co0 + u) * Cin + ci) * 3 + k] : 0.f;
    }

    u64t acc[4][4];
    #pragma unroll
    for (int j = 0; j < 4; j++)
        #pragma unroll
        for (int u = 0; u < 4; u++) acc[j][u] = 0ull;

    const int ntile = CinPad / CT;

    auto stage = [&](int t, int buf) {
        float* xb = xs + buf * (CT * TW);
        int ci0 = t * CT;
        #pragma unroll
        for (int ci = 0; ci < CT; ci++) {
            int cg = ci0 + ci;
            bool cv = (cg < Cin);
            const float* row;
            if (cg < C1)      row = src1 + (size_t)(b * C1 + cg) * Lin;
            else if (cv)      row = src2 + (size_t)(b * C2 + (cg - C1)) * Lin;
            else              row = src1;
            unsigned sb = (unsigned)__cvta_generic_to_shared(xb + ci * TW);
            for (int v = tid; v < NV; v += 256) {
                int p   = hs + v * 4;
                int okb = (cv && p >= 0 && p < Lin) ? 16 : 0;
                int pc  = min(max(p, 0), Lin - 4);
                cp16(sb + v * 16, row + pc, okb);
            }
        }
    };

    stage(0, 0);
    asm volatile("cp.async.commit_group;");

    for (int t = 0; t < ntile; t++) {
        asm volatile("cp.async.wait_group 0;");
        __syncthreads();
        if (t + 1 < ntile) {
            stage(t + 1, (t + 1) & 1);
            asm volatile("cp.async.commit_group;");
        }
        const float* xbc = xs + (t & 1) * (CT * TW);
        #pragma unroll
        for (int ci = 0; ci < CT; ci++) {
            int gci = t * CT + ci;
            const float* xr = xbc + ci * TW + tid * 4 * STRIDE;
            float xv[XN];
            {
                float4 a0 = *(const float4*)xr;
                float4 a1 = *(const float4*)(xr + 4);
                xv[0] = a0.x; xv[1] = a0.y; xv[2] = a0.z; xv[3] = a0.w;
                xv[4] = a1.x; xv[5] = a1.y; xv[6] = a1.z; xv[7] = a1.w;
                if (STRIDE == 1) {
                    xv[8] = xr[8];
                } else {
                    float4 a2 = *(const float4*)(xr + 8);
                    xv[8] = a2.x; xv[9] = a2.y; xv[10] = a2.z; xv[11] = a2.w;
                    xv[12] = 0.f;
                }
            }
            const u64t* wrow = (const u64t*)(ws + gci * 24);
            #pragma unroll
            for (int k = 0; k < 3; k++) {
                u64t w0 = wrow[k * 4 + 0], w1 = wrow[k * 4 + 1];
                u64t w2 = wrow[k * 4 + 2], w3 = wrow[k * 4 + 3];
                #pragma unroll
                for (int j = 0; j < 4; j++) {
                    float xsc = xv[j * STRIDE + k + 3];
                    u64t xq;
                    PACK2(xq, xsc, xsc);
                    FMA2(acc[j][0], xq, w0);
                    FMA2(acc[j][1], xq, w1);
                    FMA2(acc[j][2], xq, w2);
                    FMA2(acc[j][3], xq, w3);
                }
            }
        }
    }

    // epilogue: bias + raw store + fused BN-stat reduction
    const int lid = tid & 31;
    #pragma unroll
    for (int u = 0; u < 4; u++) {
        float o0[4], o1[4];
        #pragma unroll
        for (int j = 0; j < 4; j++) UNPACK2(o0[j], o1[j], acc[j][u]);
        int c0 = co0 + 2 * u;
        float b0 = bias[c0], b1 = bias[c0 + 1];
        float s0 = 0.f, q0 = 0.f, s1 = 0.f, q1 = 0.f;
        #pragma unroll
        for (int j = 0; j < 4; j++) {
            o0[j] += b0; o1[j] += b1;
            s0 += o0[j]; q0 += o0[j] * o0[j];
            s1 += o1[j]; q1 += o1[j] * o1[j];
        }
        *(float4*)&y[((size_t)(b * (gridDim.y * 8) + c0)) * Lout + P0 + tid * 4] =
            make_float4(o0[0], o0[1], o0[2], o0[3]);
        *(float4*)&y[((size_t)(b * (gridDim.y * 8) + c0 + 1)) * Lout + P0 + tid * 4] =
            make_float4(o1[0], o1[1], o1[2], o1[3]);
        unsigned full = 0xffffffffu;
        #pragma unroll
        for (int o = 16; o > 0; o >>= 1) {
            s0 += __shfl_down_sync(full, s0, o);
            q0 += __shfl_down_sync(full, q0, o);
            s1 += __shfl_down_sync(full, s1, o);
            q1 += __shfl_down_sync(full, q1, o);
        }
        if (lid == 0) {
            atomicAdd(&redS[2 * u], s0);     atomicAdd(&redQ[2 * u], q0);
            atomicAdd(&redS[2 * u + 1], s1); atomicAdd(&redQ[2 * u + 1], q1);
        }
    }
    __syncthreads();
    if (tid < 8) {
        atomicAdd(&gsum[co0 + tid], redS[tid]);
        atomicAdd(&gsqs[co0 + tid], redQ[tid]);
    }
}

// ---------------------------------------------------------------------------
// BN apply -> separate output (same resolution)
// ---------------------------------------------------------------------------
__global__ __launch_bounds__(256)
void bn_out_kernel(const float* __restrict__ raw, float* __restrict__ out,
                   int C, int L,
                   const float* __restrict__ ssum, const float* __restrict__ sqs,
                   const float* __restrict__ g, const float* __restrict__ be,
                   float invn)
{
    size_t i4 = (size_t)blockIdx.x * 256 + threadIdx.x;
    int c = (int)((i4 * 4) / (size_t)L) % C;
    float m   = ssum[c] * invn;
    float var = sqs[c] * invn - m * m;
    float sc  = g[c] * rsqrtf(var + EPSV);
    float sh  = be[c] - sc * m;
    float4 v = ((const float4*)raw)[i4];
    float4 o;
    o.x = bnl(v.x, sc, sh); o.y = bnl(v.y, sc, sh);
    o.z = bnl(v.z, sc, sh); o.w = bnl(v.w, sc, sh);
    ((float4*)out)[i4] = o;
}

// ---------------------------------------------------------------------------
// BN apply + nearest-upsample x2 -> separate output (double resolution)
// ---------------------------------------------------------------------------
__global__ __launch_bounds__(256)
void bn_up2_kernel(const float* __restrict__ raw, float* __restrict__ out,
                   int C, int Lin,
                   const float* __restrict__ ssum, const float* __restrict__ sqs,
                   const float* __restrict__ g, const float* __restrict__ be,
                   float invn)
{
    size_t i2 = (size_t)blockIdx.x * 256 + threadIdx.x;   // over B*C*Lin/2
    int c = (int)((i2 * 2) / (size_t)Lin) % C;
    float m   = ssum[c] * invn;
    float var = sqs[c] * invn - m * m;
    float sc  = g[c] * rsqrtf(var + EPSV);
    float sh  = be[c] - sc * m;
    float2 v = ((const float2*)raw)[i2];
    float a = bnl(v.x, sc, sh);
    float d = bnl(v.y, sc, sh);
    ((float4*)out)[i2] = make_float4(a, a, d, d);
}

// ---------------------------------------------------------------------------
// BN batch-stat reduce (flow head only, C=2)
// ---------------------------------------------------------------------------
__global__ __launch_bounds__(256)
void reduce_kernel(const float* __restrict__ y, int C, int L,
                   float* __restrict__ s_out, float* __restrict__ q_out)
{
    int c = blockIdx.x, b = blockIdx.y;
    const float* p = y + ((size_t)(b * C + c)) * L;
    float s = 0.f, q = 0.f;
    for (int i = threadIdx.x * 4; i < L; i += 1024) {
        float4 v = *(const float4*)(p + i);
        s += v.x + v.y + v.z + v.w;
        q += v.x * v.x + v.y * v.y + v.z * v.z + v.w * v.w;
    }
    unsigned full = 0xffffffffu;
    #pragma unroll
    for (int o = 16; o > 0; o >>= 1) {
        s += __shfl_down_sync(full, s, o);
        q += __shfl_down_sync(full, q, o);
    }
    __shared__ float shs[8], shq[8];
    int wid = threadIdx.x >> 5, lid = threadIdx.x & 31;
    if (lid == 0) { shs[wid] = s; shq[wid] = q; }
    __syncthreads();
    if (threadIdx.x == 0) {
        float ts = 0.f, tq = 0.f;
        #pragma unroll
        for (int i = 0; i < 8; i++) { ts += shs[i]; tq += shq[i]; }
        atomicAdd(&s_out[c], ts);
        atomicAdd(&q_out[c], tq);
    }
}

// ---------------------------------------------------------------------------
// Fusion: banded correlation, K=3 patch, D=5, on raw enc2 output with BN
// fused into staging. Channel-split over blockIdx.z (64 ch each), partial
// results atomically accumulated into pre-zeroed featup (B, 11, 4096),
// written duplicated (pre-upsampled).
// ---------------------------------------------------------------------------
__global__ __launch_bounds__(128)
void fusion_kernel(const float* __restrict__ f2r, float* __restrict__ featup,
                   const float* __restrict__ ssum, const float* __restrict__ sqs,
                   const float* __restrict__ gamma, const float* __restrict__ beta,
                   float invn)
{
    const int Nn = 2048, C = 256;
    const int b   = blockIdx.y;
    const int i0  = blockIdx.x * 128;
    const int cb  = blockIdx.z * 64;      // channel chunk base
    const int tid = threadIdx.x;
    const int i   = i0 + tid;
    __shared__ float tile[16][144];
    __shared__ float csc[64], csh[64];

    if (tid < 64) {
        int c = cb + tid;
        float m = ssum[c] * invn;
        float var = sqs[c] * invn - m * m;
        float sc = gamma[c] * rsqrtf(var + EPSV);
        csc[tid] = sc;
        csh[tid] = beta[c] - sc * m;
    }

    float acc[11];
    #pragma unroll
    for (int d = 0; d < 11; d++) acc[d] = 0.f;

    const bool interior = (i >= 5) && (i <= Nn - 6);

    for (int c0 = 0; c0 < 64; c0 += 16) {
        __syncthreads();
        for (int idx = tid; idx < 16 * 140; idx += 128) {
            int c = idx / 140, off = idx - c * 140;
            int p = i0 - 6 + off;
            p = min(max(p, 0), Nn - 1);
            float r = f2r[((size_t)(b * C + cb + c0 + c)) * Nn + p];
            tile[c][off] = bnl(r, csc[c0 + c], csh[c0 + c]);
        }
        __syncthreads();
        for (int c = 0; c < 16; c++) {
            float v[13];
            #pragma unroll
            for (int m = 0; m < 13; m++) v[m] = tile[c][tid + m];
            float A0 = v[5], A1 = v[6], A2 = v[7];
            if (interior) {
                #pragma unroll
                for (int dd = 0; dd < 11; dd++)
                    acc[dd] += A0 * v[dd] + A1 * v[dd + 1] + A2 * v[dd + 2];
            } else {
                for (int dd = 0; dd < 11; dd++) {
                    int j = i + dd - 5;
                    j = min(max(j, 0), Nn - 1);
                    int o0 = max(j - 1, 0) - i0 + 6;
                    int o1 = j - i0 + 6;
                    int o2 = min(j + 1, Nn - 1) - i0 + 6;
                    acc[dd] += A0 * tile[c][o0] + A1 * tile[c][o1] + A2 * tile[c][o2];
                }
            }
        }
    }
    #pragma unroll
    for (int dd = 0; dd < 11; dd++) {
        float* fo = &featup[((size_t)(b * 11 + dd)) * 4096 + 2 * i];
        atomicAdd(fo, acc[dd]);
        atomicAdd(fo + 1, acc[dd]);
    }
}

// ---------------------------------------------------------------------------
// Flow head: K=1 conv over concat(x1 raw, up(bn(d0))). One thread computes
// the upsample-twin positions (2i, 2i+1) sharing all d0 loads.
// ---------------------------------------------------------------------------
__global__ __launch_bounds__(256)
void flow_conv_kernel(const float* __restrict__ x1, const float* __restrict__ d0,
                      const float* __restrict__ w, const float* __restrict__ bias,
                      const float* __restrict__ ssum, const float* __restrict__ sqs,
                      const float* __restrict__ gamma, const float* __restrict__ beta,
                      float invn,
                      float* __restrict__ out)
{
    const int Nn = 16384;
    __shared__ float csc[128], csh[128];
    int tid = threadIdx.x;
    if (tid < 128) {
        float m = ssum[tid] * invn;
        float var = sqs[tid] * invn - m * m;
        float sc = gamma[tid] * rsqrtf(var + EPSV);
        csc[tid] = sc;
        csh[tid] = beta[tid] - sc * m;
    }
    __syncthreads();

    int b = blockIdx.y;
    int i = blockIdx.x * 256 + tid;          // 0..8191
    float2 xv = ((const float2*)&x1[(size_t)b * Nn])[i];
    float a00 = w[0] * xv.x, a01 = w[0] * xv.y;
    float a10 = w[129] * xv.x, a11 = w[129] * xv.y;
    const float* dp = d0 + (size_t)b * 128 * 8192 + i;
    #pragma unroll 4
    for (int ci = 0; ci < 128; ci++) {
        float r = dp[(size_t)ci * 8192];
        float v = bnl(r, csc[ci], csh[ci]);
        a00 += w[1 + ci] * v;   a01 += w[1 + ci] * v;
        a10 += w[130 + ci] * v; a11 += w[130 + ci] * v;
    }
    ((float2*)&out[((size_t)(b * 2 + 0)) * Nn])[i] = make_float2(a00 + bias[0], a01 + bias[0]);
    ((float2*)&out[((size_t)(b * 2 + 1)) * Nn])[i] = make_float2(a10 + bias[1], a11 + bias[1]);
}

// ---------------------------------------------------------------------------
// Flow BN apply + LeakyReLU + transpose to (B, N, 2)
// ---------------------------------------------------------------------------
__global__ __launch_bounds__(256)
void flow_apply_kernel(const float* __restrict__ fl,
                       const float* __restrict__ ssum, const float* __restrict__ sqs,
                       const float* __restrict__ gamma, const float* __restrict__ beta,
                       float* __restrict__ out, float invn)
{
    const int Nn = 16384;
    int b = blockIdx.y;
    int p = blockIdx.x * 256 + threadIdx.x;
    float m0 = ssum[0] * invn, m1 = ssum[1] * invn;
    float v0 = sqs[0] * invn - m0 * m0;
    float v1 = sqs[1] * invn - m1 * m1;
    float sc0 = gamma[0] * rsqrtf(v0 + EPSV), sh0 = beta[0] - sc0 * m0;
    float sc1 = gamma[1] * rsqrtf(v1 + EPSV), sh1 = beta[1] - sc1 * m1;
    float a = fl[((size_t)(b * 2 + 0)) * Nn + p];
    float c = fl[((size_t)(b * 2 + 1)) * Nn + p];
    float2 r;
    r.x = bnl(a, sc0, sh0);
    r.y = bnl(c, sc1, sh1);
    ((float2*)out)[(size_t)b * Nn + p] = r;
}

// ---------------------------------------------------------------------------
extern "C" void kernel_launch(void* const* d_in, const int* in_sizes, int n_in,
                              void* d_out, int out_size)
{
    (void)in_sizes; (void)n_in; (void)out_size;
    const float* scan1 = (const float*)d_in[0];
    const float* e0w = (const float*)d_in[1];
    const float* e0b = (const float*)d_in[2];
    const float* e0g = (const float*)d_in[3];
    const float* e0e = (const float*)d_in[4];
    const float* e1w = (const float*)d_in[5];
    const float* e1b = (const float*)d_in[6];
    const float* e1g = (const float*)d_in[7];
    const float* e1e = (const float*)d_in[8];
    const float* e2w = (const float*)d_in[9];
    const float* e2b = (const float*)d_in[10];
    const float* e2g = (const float*)d_in[11];
    const float* e2e = (const float*)d_in[12];
    const float* d1w = (const float*)d_in[13];
    const float* d1b = (const float*)d_in[14];
    const float* d1g = (const float*)d_in[15];
    const float* d1e = (const float*)d_in[16];
    const float* d0w = (const float*)d_in[17];
    const float* d0b = (const float*)d_in[18];
    const float* d0g = (const float*)d_in[19];
    const float* d0e = (const float*)d_in[20];
    const float* fw  = (const float*)d_in[21];
    const float* fb  = (const float*)d_in[22];
    const float* fg  = (const float*)d_in[23];
    const float* fe  = (const float*)d_in[24];

    float* base = nullptr;
    cudaGetSymbolAddress((void**)&base, g_scratch);
    float* f0r    = base + OFF_F0R;
    float* t0     = base + OFF_T0;
    float* f1r    = base + OFF_F1R;
    float* t1     = base + OFF_T1;
    float* f2r    = base + OFF_F2R;
    float* featup = base + OFF_FEATUP;
    float* d1r    = base + OFF_D1R;
    float* d1up   = base + OFF_D1UP;
    float* d0r    = base + OFF_D0R;
    float* fl     = base + OFF_FL;
    float* sum    = base + OFF_SUM;
    float* sqs    = base + OFF_SQS;

    const float i0n = 1.f / (8.f * 8192.f);
    const float i1n = 1.f / (8.f * 4096.f);
    const float i2n = 1.f / (8.f * 2048.f);

    // dynamic smem sizes (bytes): CinPad*24*4 + 2*CT*TW*4
    const int SM_E0 = (1 * 24 + 2 * 1 * 2056) * 4;     // 16544
    const int SM_E1 = (64 * 24 + 2 * 2 * 2056) * 4;    // 39040
    const int SM_E2 = (128 * 24 + 2 * 2 * 2056) * 4;   // 45184
    const int SM_D1 = (140 * 24 + 2 * 4 * 1032) * 4;   // 46464
    const int SM_D0 = (192 * 24 + 2 * 4 * 1032) * 4;   // 51456
    cudaFuncSetAttribute(conv3_cp<2, 1>, cudaFuncAttributeMaxDynamicSharedMemorySize, SM_E0);
    cudaFuncSetAttribute(conv3_cp<2, 2>, cudaFuncAttributeMaxDynamicSharedMemorySize, SM_E2);
    cudaFuncSetAttribute(conv3_cp<1, 4>, cudaFuncAttributeMaxDynamicSharedMemorySize, SM_D0);

    zero_kernel<<<6, 256>>>(sum, 1412);
    zero_kernel<<<1408, 256>>>(featup, 360448);

    // enc0: scan1 (B,1,16384) -> f0r (B,64,8192)
    conv3_cp<2, 1><<<dim3(8, 8, 8), 256, SM_E0>>>(
        scan1, 1, nullptr, 0, 16384, 8192, 1, 1,
        e0w, e0b, f0r, sum + 0, sqs + 0);
    bn_out_kernel<<<4096, 256>>>(f0r, t0, 64, 8192, sum + 0, sqs + 0, e0g, e0e, i0n);

    // enc1: t0 -> f1r (B,128,4096)
    conv3_cp<2, 2><<<dim3(4, 16, 8), 256, SM_E1>>>(
        t0, 64, nullptr, 0, 8192, 4096, 64, 64,
        e1w, e1b, f1r, sum + 64, sqs + 64);
    bn_out_kernel<<<4096, 256>>>(f1r, t1, 128, 4096, sum + 64, sqs + 64, e1g, e1e, i1n);

    // enc2: t1 -> f2r (B,256,2048)
    conv3_cp<2, 2><<<dim3(2, 32, 8), 256, SM_E2>>>(
        t1, 128, nullptr, 0, 4096, 2048, 128, 128,
        e2w, e2b, f2r, sum + 192, sqs + 192);

    // fusion on bn(f2r) -> featup (B,11,4096), pre-upsampled, channel-split
    fusion_kernel<<<dim3(16, 8, 4), 128>>>(f2r, featup,
                                           sum + 192, sqs + 192, e2g, e2e, i2n);

    // dec1: concat(t1[128], featup[11]) -> d1r (B,128,4096)
    conv3_cp<1, 4><<<dim3(4, 16, 8), 256, SM_D1>>>(
        t1, 128, featup, 11, 4096, 4096, 139, 140,
        d1w, d1b, d1r, sum + 448, sqs + 448);
    bn_up2_kernel<<<8192, 256>>>(d1r, d1up, 128, 4096, sum + 448, sqs + 448, d1g, d1e, i1n);

    // dec0: concat(t0[64], d1up[128]) -> d0r (B,128,8192)
    conv3_cp<1, 4><<<dim3(8, 16, 8), 256, SM_D0>>>(
        t0, 64, d1up, 128, 8192, 8192, 192, 192,
        d0w, d0b, d0r, sum + 576, sqs + 576);

    // flow head
    flow_conv_kernel<<<dim3(32, 8), 256>>>(scan1, d0r, fw, fb,
                                           sum + 576, sqs + 576, d0g, d0e, i0n, fl);
    reduce_kernel<<<dim3(2, 8), 256>>>(fl, 2, 16384, sum + 704, sqs + 704);
    flow_apply_kernel<<<dim3(64, 8), 256>>>(fl, sum + 704, sqs + 704, fg, fe,
                                            (float*)d_out, 1.f / (8.f * 16384.f));
}

// round 7
// speedup vs baseline: 2.5745x; 1.0133x over previous
#include <cuda_runtime.h>
#include <cstdint>

// ---------------------------------------------------------------------------
// Flow net R7: 8pos x 8outch per thread (fma-bound inner loop), cp.async
// double-buffer, fused BN stats, channel-parallel fusion, paired flow head.
// ---------------------------------------------------------------------------

#define EPSV   1e-5f
#define SLOPEV 0.01f

// scratch layout (floats)
#define OFF_F0R    0u          // raw enc0 out      8*64*8192  = 4194304
#define OFF_T0     4194304u    // bn(f0)
#define OFF_F1R    8388608u    // raw enc1 out      8*128*4096 = 4194304
#define OFF_T1     12582912u   // bn(f1)
#define OFF_F2R    16777216u   // raw enc2 out      8*256*2048 = 4194304
#define OFF_FEATUP 20971520u   // fusion out, upsampled  8*11*4096 = 360448
#define OFF_D1R    21331968u   // raw dec1 out      4194304
#define OFF_D1UP   25526272u   // bn(d1) upsampled  8*128*8192 = 8388608
#define OFF_D0R    33914880u   // raw dec0 out      8388608
#define OFF_FL     42303488u   // flow raw          262144
#define OFF_SUM    42565632u   // 706
#define OFF_SQS    42566338u   // 706
#define SCRATCH_TOTAL 42567044u

__device__ float g_scratch[SCRATCH_TOTAL];

typedef unsigned long long u64t;

#define FMA2(acc, x, w) \
    asm("fma.rn.f32x2 %0, %1, %2, %0;" : "+l"(acc) : "l"(x), "l"(w))
#define PACK2(out, lo, hi) \
    asm("mov.b64 %0, {%1, %2};" : "=l"(out) : "f"(lo), "f"(hi))
#define UNPACK2(lo, hi, in) \
    asm("mov.b64 {%0, %1}, %2;" : "=f"(lo), "=f"(hi) : "l"(in))

__device__ __forceinline__ float bnl(float r, float sc, float sh) {
    float a = sc * r + sh;
    return a >= 0.f ? a : SLOPEV * a;
}

__device__ __forceinline__ void cp16(unsigned dst, const float* src, int bytes) {
    asm volatile("cp.async.ca.shared.global [%0], [%1], 16, %2;"
                 :: "r"(dst), "l"(src), "r"(bytes));
}

// ---------------------------------------------------------------------------
__global__ void zero_kernel(float* p, int n) {
    int i = blockIdx.x * 256 + threadIdx.x;
    if (i < n) p[i] = 0.f;
}

// ---------------------------------------------------------------------------
// K=3 conv, cp.async double-buffered. 256 threads -> 2048 positions x 8 outch.
// Each thread: 8 consecutive positions x 8 out channels (32 u64 f32x2 accs).
// src1/src2 full-resolution, pre-transformed. Pure-copy staging.
// Epilogue: bias + store raw + fused BN-stat partial reduction.
// ---------------------------------------------------------------------------
template<int STRIDE, int CT>
__global__ __launch_bounds__(256, 2)
void conv3_cp(const float* __restrict__ src1, int C1,
              const float* __restrict__ src2, int C2,
              int Lin, int Lout, int Cin, int CinPad,
              const float* __restrict__ w, const float* __restrict__ bias,
              float* __restrict__ y,
              float* __restrict__ gsum, float* __restrict__ gsqs)
{
    constexpr int TP = 2048;
    constexpr int TW = TP * STRIDE + 8;
    constexpr int NV = TW / 4;
    constexpr int XN = 8 * STRIDE + 5;   // 13 (s1) / 21 (s2)

    extern __shared__ float sh[];
    __shared__ float redS[8], redQ[8];

    const int tid = threadIdx.x;
    const int P0  = blockIdx.x * TP;
    const int co0 = blockIdx.y * 8;
    const int b   = blockIdx.z;
    const int hs  = P0 * STRIDE - 4;
    const int wsN = CinPad * 24;
    float* ws = sh;
    float* xs = sh + wsN;

    if (tid < 8) { redS[tid] = 0.f; redQ[tid] = 0.f; }

    // stage ALL weights once: ws[ci*24 + k*8 + u] = w[co0+u][ci][k]
    for (int idx = tid; idx < wsN; idx += 256) {
        int ci = idx / 24;
        int r  = idx - ci * 24;
        int k  = r >> 3, u = r & 7;
        ws[idx] = (ci < Cin) ? w[((size_t)(co0 + u) * Cin + ci) * 3 + k] : 0.f;
    }

    u64t acc[8][4];
    #pragma unroll
    for (int j = 0; j < 8; j++)
        #pragma unroll
        for (int u = 0; u < 4; u++) acc[j][u] = 0ull;

    const int ntile = CinPad / CT;

    auto stage = [&](int t, int buf) {
        float* xb = xs + buf * (CT * TW);
        int ci0 = t * CT;
        #pragma unroll
        for (int ci = 0; ci < CT; ci++) {
            int cg = ci0 + ci;
            bool cv = (cg < Cin);
            const float* row;
            if (cg < C1)      row = src1 + (size_t)(b * C1 + cg) * Lin;
            else if (cv)      row = src2 + (size_t)(b * C2 + (cg - C1)) * Lin;
            else              row = src1;
            unsigned sb = (unsigned)__cvta_generic_to_shared(xb + ci * TW);
            for (int v = tid; v < NV; v += 256) {
                int p   = hs + v * 4;
                int okb = (cv && p >= 0 && p < Lin) ? 16 : 0;
                int pc  = min(max(p, 0), Lin - 4);
                cp16(sb + v * 16, row + pc, okb);
            }
        }
    };

    stage(0, 0);
    asm volatile("cp.async.commit_group;");

    for (int t = 0; t < ntile; t++) {
        asm volatile("cp.async.wait_group 0;");
        __syncthreads();
        if (t + 1 < ntile) {
            stage(t + 1, (t + 1) & 1);
            asm volatile("cp.async.commit_group;");
        }
        const float* xbc = xs + (t & 1) * (CT * TW);
        #pragma unroll
        for (int ci = 0; ci < CT; ci++) {
            int gci = t * CT + ci;
            const float* xr = xbc + ci * TW + tid * 8 * STRIDE;
            float xv[XN];
            if (STRIDE == 1) {
                float4 a0 = *(const float4*)xr;
                float4 a1 = *(const float4*)(xr + 4);
                float4 a2 = *(const float4*)(xr + 8);
                xv[0] = a0.x;  xv[1] = a0.y;  xv[2] = a0.z;  xv[3] = a0.w;
                xv[4] = a1.x;  xv[5] = a1.y;  xv[6] = a1.z;  xv[7] = a1.w;
                xv[8] = a2.x;  xv[9] = a2.y;  xv[10] = a2.z; xv[11] = a2.w;
                xv[12] = xr[12];
            } else {
                float4 a0 = *(const float4*)xr;
                float4 a1 = *(const float4*)(xr + 4);
                float4 a2 = *(const float4*)(xr + 8);
                float4 a3 = *(const float4*)(xr + 12);
                float4 a4 = *(const float4*)(xr + 16);
                xv[0] = a0.x;   xv[1] = a0.y;   xv[2] = a0.z;   xv[3] = a0.w;
                xv[4] = a1.x;   xv[5] = a1.y;   xv[6] = a1.z;   xv[7] = a1.w;
                xv[8] = a2.x;   xv[9] = a2.y;   xv[10] = a2.z;  xv[11] = a2.w;
                xv[12] = a3.x;  xv[13] = a3.y;  xv[14] = a3.z;  xv[15] = a3.w;
                xv[16] = a4.x;  xv[17] = a4.y;  xv[18] = a4.z;  xv[19] = a4.w;
                xv[20] = xr[20];
            }
            const u64t* wrow = (const u64t*)(ws + gci * 24);
            #pragma unroll
            for (int k = 0; k < 3; k++) {
                u64t w0 = wrow[k * 4 + 0], w1 = wrow[k * 4 + 1];
                u64t w2 = wrow[k * 4 + 2], w3 = wrow[k * 4 + 3];
                #pragma unroll
                for (int j = 0; j < 8; j++) {
                    float xsc = xv[j * STRIDE + k + 3];
                    u64t xq;
                    PACK2(xq, xsc, xsc);
                    FMA2(acc[j][0], xq, w0);
                    FMA2(acc[j][1], xq, w1);
                    FMA2(acc[j][2], xq, w2);
                    FMA2(acc[j][3], xq, w3);
                }
            }
        }
    }

    // epilogue: bias + raw store + fused BN-stat reduction
    const int lid = tid & 31;
    #pragma unroll
    for (int u = 0; u < 4; u++) {
        float o0[8], o1[8];
        #pragma unroll
        for (int j = 0; j < 8; j++) UNPACK2(o0[j], o1[j], acc[j][u]);
        int c0 = co0 + 2 * u;
        float b0 = bias[c0], b1 = bias[c0 + 1];
        float s0 = 0.f, q0 = 0.f, s1 = 0.f, q1 = 0.f;
        #pragma unroll
        for (int j = 0; j < 8; j++) {
            o0[j] += b0; o1[j] += b1;
            s0 += o0[j]; q0 += o0[j] * o0[j];
            s1 += o1[j]; q1 += o1[j] * o1[j];
        }
        float* y0 = &y[((size_t)(b * (gridDim.y * 8) + c0)) * Lout + P0 + tid * 8];
        float* y1 = &y[((size_t)(b * (gridDim.y * 8) + c0 + 1)) * Lout + P0 + tid * 8];
        *(float4*)y0       = make_float4(o0[0], o0[1], o0[2], o0[3]);
        *(float4*)(y0 + 4) = make_float4(o0[4], o0[5], o0[6], o0[7]);
        *(float4*)y1       = make_float4(o1[0], o1[1], o1[2], o1[3]);
        *(float4*)(y1 + 4) = make_float4(o1[4], o1[5], o1[6], o1[7]);
        unsigned full = 0xffffffffu;
        #pragma unroll
        for (int o = 16; o > 0; o >>= 1) {
            s0 += __shfl_down_sync(full, s0, o);
            q0 += __shfl_down_sync(full, q0, o);
            s1 += __shfl_down_sync(full, s1, o);
            q1 += __shfl_down_sync(full, q1, o);
        }
        if (lid == 0) {
            atomicAdd(&redS[2 * u], s0);     atomicAdd(&redQ[2 * u], q0);
            atomicAdd(&redS[2 * u + 1], s1); atomicAdd(&redQ[2 * u + 1], q1);
        }
    }
    __syncthreads();
    if (tid < 8) {
        atomicAdd(&gsum[co0 + tid], redS[tid]);
        atomicAdd(&gsqs[co0 + tid], redQ[tid]);
    }
}

// ---------------------------------------------------------------------------
// BN apply -> separate output (same resolution)
// ---------------------------------------------------------------------------
__global__ __launch_bounds__(256)
void bn_out_kernel(const float* __restrict__ raw, float* __restrict__ out,
                   int C, int L,
                   const float* __restrict__ ssum, const float* __restrict__ sqs,
                   const float* __restrict__ g, const float* __restrict__ be,
                   float invn)
{
    size_t i4 = (size_t)blockIdx.x * 256 + threadIdx.x;
    int c = (int)((i4 * 4) / (size_t)L) % C;
    float m   = ssum[c] * invn;
    float var = sqs[c] * invn - m * m;
    float sc  = g[c] * rsqrtf(var + EPSV);
    float sh  = be[c] - sc * m;
    float4 v = ((const float4*)raw)[i4];
    float4 o;
    o.x = bnl(v.x, sc, sh); o.y = bnl(v.y, sc, sh);
    o.z = bnl(v.z, sc, sh); o.w = bnl(v.w, sc, sh);
    ((float4*)out)[i4] = o;
}

// ---------------------------------------------------------------------------
// BN apply + nearest-upsample x2 -> separate output (double resolution)
// ---------------------------------------------------------------------------
__global__ __launch_bounds__(256)
void bn_up2_kernel(const float* __restrict__ raw, float* __restrict__ out,
                   int C, int Lin,
                   const float* __restrict__ ssum, const float* __restrict__ sqs,
                   const float* __restrict__ g, const float* __restrict__ be,
                   float invn)
{
    size_t i2 = (size_t)blockIdx.x * 256 + threadIdx.x;   // over B*C*Lin/2
    int c = (int)((i2 * 2) / (size_t)Lin) % C;
    float m   = ssum[c] * invn;
    float var = sqs[c] * invn - m * m;
    float sc  = g[c] * rsqrtf(var + EPSV);
    float sh  = be[c] - sc * m;
    float2 v = ((const float2*)raw)[i2];
    float a = bnl(v.x, sc, sh);
    float d = bnl(v.y, sc, sh);
    ((float4*)out)[i2] = make_float4(a, a, d, d);
}

// ---------------------------------------------------------------------------
// BN batch-stat reduce (flow head only, C=2)
// ---------------------------------------------------------------------------
__global__ __launch_bounds__(256)
void reduce_kernel(const float* __restrict__ y, int C, int L,
                   float* __restrict__ s_out, float* __restrict__ q_out)
{
    int c = blockIdx.x, b = blockIdx.y;
    const float* p = y + ((size_t)(b * C + c)) * L;
    float s = 0.f, q = 0.f;
    for (int i = threadIdx.x * 4; i < L; i += 1024) {
        float4 v = *(const float4*)(p + i);
        s += v.x + v.y + v.z + v.w;
        q += v.x * v.x + v.y * v.y + v.z * v.z + v.w * v.w;
    }
    unsigned full = 0xffffffffu;
    #pragma unroll
    for (int o = 16; o > 0; o >>= 1) {
        s += __shfl_down_sync(full, s, o);
        q += __shfl_down_sync(full, q, o);
    }
    __shared__ float shs[8], shq[8];
    int wid = threadIdx.x >> 5, lid = threadIdx.x & 31;
    if (lid == 0) { shs[wid] = s; shq[wid] = q; }
    __syncthreads();
    if (threadIdx.x == 0) {
        float ts = 0.f, tq = 0.f;
        #pragma unroll
        for (int i = 0; i < 8; i++) { ts += shs[i]; tq += shq[i]; }
        atomicAdd(&s_out[c], ts);
        atomicAdd(&q_out[c], tq);
    }
}

// ---------------------------------------------------------------------------
// Fusion: banded correlation, K=3 patch, D=5, on raw enc2 output with BN
// fused into staging. Channel-split over blockIdx.z (64 ch each), partial
// results atomically accumulated into pre-zeroed featup (B, 11, 4096),
// written duplicated (pre-upsampled).
// ---------------------------------------------------------------------------
__global__ __launch_bounds__(128)
void fusion_kernel(const float* __restrict__ f2r, float* __restrict__ featup,
                   const float* __restrict__ ssum, const float* __restrict__ sqs,
                   const float* __restrict__ gamma, const float* __restrict__ beta,
                   float invn)
{
    const int Nn = 2048, C = 256;
    const int b   = blockIdx.y;
    const int i0  = blockIdx.x * 128;
    const int cb  = blockIdx.z * 64;      // channel chunk base
    const int tid = threadIdx.x;
    const int i   = i0 + tid;
    __shared__ float tile[16][144];
    __shared__ float csc[64], csh[64];

    if (tid < 64) {
        int c = cb + tid;
        float m = ssum[c] * invn;
        float var = sqs[c] * invn - m * m;
        float sc = gamma[c] * rsqrtf(var + EPSV);
        csc[tid] = sc;
        csh[tid] = beta[c] - sc * m;
    }

    float acc[11];
    #pragma unroll
    for (int d = 0; d < 11; d++) acc[d] = 0.f;

    const bool interior = (i >= 5) && (i <= Nn - 6);

    for (int c0 = 0; c0 < 64; c0 += 16) {
        __syncthreads();
        for (int idx = tid; idx < 16 * 140; idx += 128) {
            int c = idx / 140, off = idx - c * 140;
            int p = i0 - 6 + off;
            p = min(max(p, 0), Nn - 1);
            float r = f2r[((size_t)(b * C + cb + c0 + c)) * Nn + p];
            tile[c][off] = bnl(r, csc[c0 + c], csh[c0 + c]);
        }
        __syncthreads();
        for (int c = 0; c < 16; c++) {
            float v[13];
            #pragma unroll
            for (int m = 0; m < 13; m++) v[m] = tile[c][tid + m];
            float A0 = v[5], A1 = v[6], A2 = v[7];
            if (interior) {
                #pragma unroll
                for (int dd = 0; dd < 11; dd++)
                    acc[dd] += A0 * v[dd] + A1 * v[dd + 1] + A2 * v[dd + 2];
            } else {
                for (int dd = 0; dd < 11; dd++) {
                    int j = i + dd - 5;
                    j = min(max(j, 0), Nn - 1);
                    int o0 = max(j - 1, 0) - i0 + 6;
                    int o1 = j - i0 + 6;
                    int o2 = min(j + 1, Nn - 1) - i0 + 6;
                    acc[dd] += A0 * tile[c][o0] + A1 * tile[c][o1] + A2 * tile[c][o2];
                }
            }
        }
    }
    #pragma unroll
    for (int dd = 0; dd < 11; dd++) {
        float* fo = &featup[((size_t)(b * 11 + dd)) * 4096 + 2 * i];
        atomicAdd(fo, acc[dd]);
        atomicAdd(fo + 1, acc[dd]);
    }
}

// ---------------------------------------------------------------------------
// Flow head: K=1 conv over concat(x1 raw, up(bn(d0))). One thread computes
// the upsample-twin positions (2i, 2i+1) sharing all d0 loads.
// ---------------------------------------------------------------------------
__global__ __launch_bounds__(256)
void flow_conv_kernel(const float* __restrict__ x1, const float* __restrict__ d0,
                      const float* __restrict__ w, const float* __restrict__ bias,
                      const float* __restrict__ ssum, const float* __restrict__ sqs,
                      const float* __restrict__ gamma, const float* __restrict__ beta,
                      float invn,
                      float* __restrict__ out)
{
    const int Nn = 16384;
    __shared__ float csc[128], csh[128];
    int tid = threadIdx.x;
    if (tid < 128) {
        float m = ssum[tid] * invn;
        float var = sqs[tid] * invn - m * m;
        float sc = gamma[tid] * rsqrtf(var + EPSV);
        csc[tid] = sc;
        csh[tid] = beta[tid] - sc * m;
    }
    __syncthreads();

    int b = blockIdx.y;
    int i = blockIdx.x * 256 + tid;          // 0..8191
    float2 xv = ((const float2*)&x1[(size_t)b * Nn])[i];
    float a00 = w[0] * xv.x, a01 = w[0] * xv.y;
    float a10 = w[129] * xv.x, a11 = w[129] * xv.y;
    const float* dp = d0 + (size_t)b * 128 * 8192 + i;
    #pragma unroll 4
    for (int ci = 0; ci < 128; ci++) {
        float r = dp[(size_t)ci * 8192];
        float v = bnl(r, csc[ci], csh[ci]);
        a00 += w[1 + ci] * v;   a01 += w[1 + ci] * v;
        a10 += w[130 + ci] * v; a11 += w[130 + ci] * v;
    }
    ((float2*)&out[((size_t)(b * 2 + 0)) * Nn])[i] = make_float2(a00 + bias[0], a01 + bias[0]);
    ((float2*)&out[((size_t)(b * 2 + 1)) * Nn])[i] = make_float2(a10 + bias[1], a11 + bias[1]);
}

// ---------------------------------------------------------------------------
// Flow BN apply + LeakyReLU + transpose to (B, N, 2)
// ---------------------------------------------------------------------------
__global__ __launch_bounds__(256)
void flow_apply_kernel(const float* __restrict__ fl,
                       const float* __restrict__ ssum, const float* __restrict__ sqs,
                       const float* __restrict__ gamma, const float* __restrict__ beta,
                       float* __restrict__ out, float invn)
{
    const int Nn = 16384;
    int b = blockIdx.y;
    int p = blockIdx.x * 256 + threadIdx.x;
    float m0 = ssum[0] * invn, m1 = ssum[1] * invn;
    float v0 = sqs[0] * invn - m0 * m0;
    float v1 = sqs[1] * invn - m1 * m1;
    float sc0 = gamma[0] * rsqrtf(v0 + EPSV), sh0 = beta[0] - sc0 * m0;
    float sc1 = gamma[1] * rsqrtf(v1 + EPSV), sh1 = beta[1] - sc1 * m1;
    float a = fl[((size_t)(b * 2 + 0)) * Nn + p];
    float c = fl[((size_t)(b * 2 + 1)) * Nn + p];
    float2 r;
    r.x = bnl(a, sc0, sh0);
    r.y = bnl(c, sc1, sh1);
    ((float2*)out)[(size_t)b * Nn + p] = r;
}

// ---------------------------------------------------------------------------
extern "C" void kernel_launch(void* const* d_in, const int* in_sizes, int n_in,
                              void* d_out, int out_size)
{
    (void)in_sizes; (void)n_in; (void)out_size;
    const float* scan1 = (const float*)d_in[0];
    const float* e0w = (const float*)d_in[1];
    const float* e0b = (const float*)d_in[2];
    const float* e0g = (const float*)d_in[3];
    const float* e0e = (const float*)d_in[4];
    const float* e1w = (const float*)d_in[5];
    const float* e1b = (const float*)d_in[6];
    const float* e1g = (const float*)d_in[7];
    const float* e1e = (const float*)d_in[8];
    const float* e2w = (const float*)d_in[9];
    const float* e2b = (const float*)d_in[10];
    const float* e2g = (const float*)d_in[11];
    const float* e2e = (const float*)d_in[12];
    const float* d1w = (const float*)d_in[13];
    const float* d1b = (const float*)d_in[14];
    const float* d1g = (const float*)d_in[15];
    const float* d1e = (const float*)d_in[16];
    const float* d0w = (const float*)d_in[17];
    const float* d0b = (const float*)d_in[18];
    const float* d0g = (const float*)d_in[19];
    const float* d0e = (const float*)d_in[20];
    const float* fw  = (const float*)d_in[21];
    const float* fb  = (const float*)d_in[22];
    const float* fg  = (const float*)d_in[23];
    const float* fe  = (const float*)d_in[24];

    float* base = nullptr;
    cudaGetSymbolAddress((void**)&base, g_scratch);
    float* f0r    = base + OFF_F0R;
    float* t0     = base + OFF_T0;
    float* f1r    = base + OFF_F1R;
    float* t1     = base + OFF_T1;
    float* f2r    = base + OFF_F2R;
    float* featup = base + OFF_FEATUP;
    float* d1r    = base + OFF_D1R;
    float* d1up   = base + OFF_D1UP;
    float* d0r    = base + OFF_D0R;
    float* fl     = base + OFF_FL;
    float* sum    = base + OFF_SUM;
    float* sqs    = base + OFF_SQS;

    const float i0n = 1.f / (8.f * 8192.f);
    const float i1n = 1.f / (8.f * 4096.f);
    const float i2n = 1.f / (8.f * 2048.f);

    // dynamic smem sizes (bytes): CinPad*24*4 + 2*CT*TW*4
    const int SM_E0 = (1 * 24 + 2 * 1 * 4104) * 4;     // 32928
    const int SM_E1 = (64 * 24 + 2 * 2 * 4104) * 4;    // 71808
    const int SM_E2 = (128 * 24 + 2 * 2 * 4104) * 4;   // 77952
    const int SM_D1 = (140 * 24 + 2 * 4 * 2056) * 4;   // 79232
    const int SM_D0 = (192 * 24 + 2 * 4 * 2056) * 4;   // 84224
    cudaFuncSetAttribute(conv3_cp<2, 1>, cudaFuncAttributeMaxDynamicSharedMemorySize, SM_E0);
    cudaFuncSetAttribute(conv3_cp<2, 2>, cudaFuncAttributeMaxDynamicSharedMemorySize, SM_E2);
    cudaFuncSetAttribute(conv3_cp<1, 4>, cudaFuncAttributeMaxDynamicSharedMemorySize, SM_D0);

    zero_kernel<<<6, 256>>>(sum, 1412);
    zero_kernel<<<1408, 256>>>(featup, 360448);

    // enc0: scan1 (B,1,16384) -> f0r (B,64,8192)
    conv3_cp<2, 1><<<dim3(4, 8, 8), 256, SM_E0>>>(
        scan1, 1, nullptr, 0, 16384, 8192, 1, 1,
        e0w, e0b, f0r, sum + 0, sqs + 0);
    bn_out_kernel<<<4096, 256>>>(f0r, t0, 64, 8192, sum + 0, sqs + 0, e0g, e0e, i0n);

    // enc1: t0 -> f1r (B,128,4096)
    conv3_cp<2, 2><<<dim3(2, 16, 8), 256, SM_E1>>>(
        t0, 64, nullptr, 0, 8192, 4096, 64, 64,
        e1w, e1b, f1r, sum + 64, sqs + 64);
    bn_out_kernel<<<4096, 256>>>(f1r, t1, 128, 4096, sum + 64, sqs + 64, e1g, e1e, i1n);

    // enc2: t1 -> f2r (B,256,2048)
    conv3_cp<2, 2><<<dim3(1, 32, 8), 256, SM_E2>>>(
        t1, 128, nullptr, 0, 4096, 2048, 128, 128,
        e2w, e2b, f2r, sum + 192, sqs + 192);

    // fusion on bn(f2r) -> featup (B,11,4096), pre-upsampled, channel-split
    fusion_kernel<<<dim3(16, 8, 4), 128>>>(f2r, featup,
                                           sum + 192, sqs + 192, e2g, e2e, i2n);

    // dec1: concat(t1[128], featup[11]) -> d1r (B,128,4096)
    conv3_cp<1, 4><<<dim3(2, 16, 8), 256, SM_D1>>>(
        t1, 128, featup, 11, 4096, 4096, 139, 140,
        d1w, d1b, d1r, sum + 448, sqs + 448);
    bn_up2_kernel<<<8192, 256>>>(d1r, d1up, 128, 4096, sum + 448, sqs + 448, d1g, d1e, i1n);

    // dec0: concat(t0[64], d1up[128]) -> d0r (B,128,8192)
    conv3_cp<1, 4><<<dim3(4, 16, 8), 256, SM_D0>>>(
        t0, 64, d1up, 128, 8192, 8192, 192, 192,
        d0w, d0b, d0r, sum + 576, sqs + 576);

    // flow head
    flow_conv_kernel<<<dim3(32, 8), 256>>>(scan1, d0r, fw, fb,
                                           sum + 576, sqs + 576, d0g, d0e, i0n, fl);
    reduce_kernel<<<dim3(2, 8), 256>>>(fl, 2, 16384, sum + 704, sqs + 704);
    flow_apply_kernel<<<dim3(64, 8), 256>>>(fl, sum + 704, sqs + 704, fg, fe,
                                            (float*)d_out, 1.f / (8.f * 16384.f));
}